// round 1
// baseline (speedup 1.0000x reference)
#include <cuda_runtime.h>
#include <math.h>
#include <float.h>
#include <stdint.h>

// ---------------- problem constants ----------------
#define Bb   8
#define Nn   4096
#define Dd   128
#define Pp   256
#define Kk   64
#define DFF  1024
#define NCc  16
#define BP   (Bb*Pp)            // 2048 patches
#define ROWS (BP*Kk)            // 131072 fine rows
#define EPSX 1e-5f

// ---------------- scratch (__device__ globals; no allocation allowed) ----------------
__device__ int   g_fidx[BP];
__device__ float g_pcx[BP*3];
__device__ int   g_gidx[BP*Kk];
__device__ float g_pf[BP*Dd];                    // patch features (maxpooled)  [2048,128]
__device__ float g_gxyz[BP*Kk*3];                // grouped_xyz_norm            [2048,64,3]
__device__ float g_h1m[BP*DFF];                  // MLP hidden 1                [2048,1024]
__device__ float g_h2m[BP*DFF];                  // MLP hidden 2                [2048,1024]
__device__ float g_coarse[BP*NCc*3];             // coarse points               [2048,16,3]
__device__ float g_Y0[BP*DFF];                   // pf @ cw1[:128]              [2048,1024]
__device__ float g_H1[(size_t)ROWS*DFF];         // h1                          [131072,1024]
__device__ float g_H2[(size_t)ROWS*DFF];         // h2                          [131072,1024]
__device__ float g_fine[ROWS*3];                 // fine points                 [131072,3]
__device__ float g_ab[4*DFF];                    // alpha1,beta1,alpha2,beta2
__device__ float g_partial[2*BP];                // chamfer partial sums

// ---------------- BN fold precompute ----------------
__global__ void prep_kernel(const float* __restrict__ g1, const float* __restrict__ be1,
                            const float* __restrict__ m1, const float* __restrict__ v1,
                            const float* __restrict__ cb1,
                            const float* __restrict__ g2, const float* __restrict__ be2,
                            const float* __restrict__ m2, const float* __restrict__ v2,
                            const float* __restrict__ cb2) {
    int j = blockIdx.x * blockDim.x + threadIdx.x;
    if (j < DFF) {
        float a1 = g1[j] * rsqrtf(v1[j] + EPSX);
        g_ab[j]          = a1;
        g_ab[DFF + j]    = (cb1[j] - m1[j]) * a1 + be1[j];
        float a2 = g2[j] * rsqrtf(v2[j] + EPSX);
        g_ab[2*DFF + j]  = a2;
        g_ab[3*DFF + j]  = (cb2[j] - m2[j]) * a2 + be2[j];
    }
}

// ---------------- FPS (must match JAX argmax semantics bit-exactly) ----------------
__global__ void fps_kernel(const float* __restrict__ xyz) {
    int b = blockIdx.x;
    const float* X = xyz + (size_t)b * Nn * 3;
    __shared__ float mind[Nn];
    __shared__ float rv[1024];
    __shared__ int   ri[1024];
    __shared__ int   s_last;
    int tid = threadIdx.x;

    float px[4], py[4], pz[4];
#pragma unroll
    for (int i = 0; i < 4; i++) {
        int n = tid + i * 1024;
        px[i] = X[n*3+0]; py[i] = X[n*3+1]; pz[i] = X[n*3+2];
        mind[n] = 1e10f;
    }
    if (tid == 0) {
        s_last = 0;
        g_fidx[b*Pp] = 0;
        g_pcx[(b*Pp)*3+0] = X[0];
        g_pcx[(b*Pp)*3+1] = X[1];
        g_pcx[(b*Pp)*3+2] = X[2];
    }
    __syncthreads();

    for (int it = 1; it < Pp; it++) {
        int last = s_last;
        float lx = X[last*3+0], ly = X[last*3+1], lz = X[last*3+2];
        float bv = -1.0f; int bi = Nn;
#pragma unroll
        for (int i = 0; i < 4; i++) {
            int n = tid + i * 1024;
            // exact JAX order: ((dx*dx + dy*dy) + dz*dz), no FMA contraction
            float dx = __fsub_rn(px[i], lx);
            float dy = __fsub_rn(py[i], ly);
            float dz = __fsub_rn(pz[i], lz);
            float d  = __fadd_rn(__fadd_rn(__fmul_rn(dx,dx), __fmul_rn(dy,dy)), __fmul_rn(dz,dz));
            float m  = fminf(mind[n], d);
            mind[n]  = m;
            if (m > bv || (m == bv && n < bi)) { bv = m; bi = n; }
        }
        rv[tid] = bv; ri[tid] = bi;
        __syncthreads();
        for (int s = 512; s > 0; s >>= 1) {
            if (tid < s) {
                float v2 = rv[tid+s]; int i2 = ri[tid+s];
                if (v2 > rv[tid] || (v2 == rv[tid] && i2 < ri[tid])) { rv[tid] = v2; ri[tid] = i2; }
            }
            __syncthreads();
        }
        if (tid == 0) {
            int w = ri[0];
            s_last = w;
            g_fidx[b*Pp + it] = w;
            g_pcx[(b*Pp + it)*3+0] = X[w*3+0];
            g_pcx[(b*Pp + it)*3+1] = X[w*3+1];
            g_pcx[(b*Pp + it)*3+2] = X[w*3+2];
        }
        __syncthreads();
    }
}

// ---------------- kNN grouping + feature maxpool + normalized xyz ----------------
__global__ void group_kernel(const float* __restrict__ xyz, const float* __restrict__ feat) {
    int bp = blockIdx.x;
    int b  = bp / Pp;
    const float* X = xyz + (size_t)b * Nn * 3;
    __shared__ float sd[Nn];
    __shared__ float rv[256];
    __shared__ int   ri[256];
    __shared__ int   sel[Kk];
    int tid = threadIdx.x;

    float cx = g_pcx[bp*3+0], cy = g_pcx[bp*3+1], cz = g_pcx[bp*3+2];
    for (int n = tid; n < Nn; n += 256) {
        float dx = X[n*3+0] - cx, dy = X[n*3+1] - cy, dz = X[n*3+2] - cz;
        sd[n] = dx*dx + dy*dy + dz*dz;
    }
    __syncthreads();

    for (int k = 0; k < Kk; k++) {
        float bv = FLT_MAX; int bi = Nn;
        for (int n = tid; n < Nn; n += 256) {
            float v = sd[n];
            if (v < bv || (v == bv && n < bi)) { bv = v; bi = n; }
        }
        rv[tid] = bv; ri[tid] = bi;
        __syncthreads();
        for (int s = 128; s > 0; s >>= 1) {
            if (tid < s) {
                float v2 = rv[tid+s]; int i2 = ri[tid+s];
                if (v2 < rv[tid] || (v2 == rv[tid] && i2 < ri[tid])) { rv[tid] = v2; ri[tid] = i2; }
            }
            __syncthreads();
        }
        if (tid == 0) { sel[k] = ri[0]; sd[ri[0]] = FLT_MAX; }
        __syncthreads();
    }

    if (tid < Kk) {
        int idx = sel[tid];
        g_gidx[bp*Kk + tid] = idx;
        g_gxyz[(bp*Kk + tid)*3+0] = X[idx*3+0] - cx;
        g_gxyz[(bp*Kk + tid)*3+1] = X[idx*3+1] - cy;
        g_gxyz[(bp*Kk + tid)*3+2] = X[idx*3+2] - cz;
    }
    __syncthreads();

    const float* F = feat + (size_t)b * Nn * Dd;
    for (int d = tid; d < Dd; d += 256) {
        float m = -FLT_MAX;
        for (int k = 0; k < Kk; k++)
            m = fmaxf(m, F[(size_t)sel[k] * Dd + d]);
        g_pf[bp*Dd + d] = m;
    }
}

// ---------------- generic fp32 tiled GEMM: C = act( (A@B) * alpha[n] + beta[n] ) ----------------
// A [M,Kd] row-major, B [Kd,N] row-major.
#define BM 128
#define BN 128
#define BK 8
#define TM 8
#define TN 8
__global__ void gemm_kernel(const float* __restrict__ A, const float* __restrict__ B,
                            float* __restrict__ C, int M, int N, int Kd,
                            const float* __restrict__ alpha, const float* __restrict__ beta,
                            int relu) {
    __shared__ float As[BK][BM];
    __shared__ float Bs[BK][BN];
    int tid = threadIdx.x;           // 256
    int tx = tid % 16, ty = tid / 16;
    int rowBase = blockIdx.y * BM;
    int colBase = blockIdx.x * BN;

    float acc[TM][TN];
#pragma unroll
    for (int i = 0; i < TM; i++)
#pragma unroll
        for (int j = 0; j < TN; j++) acc[i][j] = 0.0f;

    int aRow  = tid >> 1;            // 0..127
    int aCol4 = (tid & 1) * 4;       // 0 or 4
    int bRow  = tid >> 5;            // 0..7
    int bCol4 = (tid & 31) * 4;      // 0..124

    for (int k0 = 0; k0 < Kd; k0 += BK) {
        {
            int gr = rowBase + aRow;
#pragma unroll
            for (int i = 0; i < 4; i++) {
                int gk = k0 + aCol4 + i;
                float v = (gr < M && gk < Kd) ? A[(size_t)gr * Kd + gk] : 0.0f;
                As[aCol4 + i][aRow] = v;
            }
        }
        {
            int gk = k0 + bRow;
#pragma unroll
            for (int i = 0; i < 4; i++) {
                int gc = colBase + bCol4 + i;
                float v = (gk < Kd && gc < N) ? B[(size_t)gk * N + gc] : 0.0f;
                Bs[bRow][bCol4 + i] = v;
            }
        }
        __syncthreads();
#pragma unroll
        for (int kk = 0; kk < BK; kk++) {
            float a[TM], bb[TN];
#pragma unroll
            for (int i = 0; i < TM; i++) a[i] = As[kk][ty*TM + i];
#pragma unroll
            for (int j = 0; j < TN; j++) bb[j] = Bs[kk][tx*TN + j];
#pragma unroll
            for (int i = 0; i < TM; i++)
#pragma unroll
                for (int j = 0; j < TN; j++) acc[i][j] += a[i] * bb[j];
        }
        __syncthreads();
    }

#pragma unroll
    for (int i = 0; i < TM; i++) {
        int r = rowBase + ty*TM + i;
        if (r >= M) continue;
#pragma unroll
        for (int j = 0; j < TN; j++) {
            int c = colBase + tx*TN + j;
            if (c >= N) continue;
            float v  = acc[i][j];
            float al = alpha ? alpha[c] : 1.0f;
            float bt = beta  ? beta[c]  : 0.0f;
            v = v * al + bt;
            if (relu) v = fmaxf(v, 0.0f);
            C[(size_t)r * N + c] = v;
        }
    }
}

// ---------------- build h1 rows from Y0 + seed + pts terms (replaces 133-K GEMM) ----------------
__global__ void h1_build_kernel(const float* __restrict__ cw1) {
    int bp  = blockIdx.x;
    int tid = threadIdx.x;               // 256
    __shared__ float y0[DFF], c0[DFF], c1[DFF], c2[DFF], c3[DFF], c4[DFF], al[DFF], bt[DFF];
    __shared__ float crs[NCc*3];

    for (int j = tid; j < DFF; j += 256) {
        y0[j] = g_Y0[(size_t)bp*DFF + j];
        c0[j] = cw1[(size_t)128*DFF + j];
        c1[j] = cw1[(size_t)129*DFF + j];
        c2[j] = cw1[(size_t)130*DFF + j];
        c3[j] = cw1[(size_t)131*DFF + j];
        c4[j] = cw1[(size_t)132*DFF + j];
        al[j] = g_ab[j];
        bt[j] = g_ab[DFF + j];
    }
    if (tid < NCc*3) crs[tid] = g_coarse[bp*NCc*3 + tid];
    __syncthreads();

    for (int k = 0; k < Kk; k++) {
        int sidx = k & 3;
        float s0 = (sidx & 1) ?  0.05f : -0.05f;   // tile(a, GRID)
        float s1 = (sidx & 2) ?  0.05f : -0.05f;   // repeat(a, GRID)
        int nc = k >> 2;
        float pxv = crs[nc*3+0], pyv = crs[nc*3+1], pzv = crs[nc*3+2];
        size_t rowoff = ((size_t)bp * Kk + k) * DFF;
        for (int j = tid; j < DFF; j += 256) {
            float pre = y0[j] + s0*c0[j] + s1*c1[j] + pxv*c2[j] + pyv*c3[j] + pzv*c4[j];
            g_H1[rowoff + j] = fmaxf(pre * al[j] + bt[j], 0.0f);
        }
    }
}

// ---------------- fine = H2 @ cw3 + cb3 + pts  (one warp per row) ----------------
__global__ void fine_kernel(const float* __restrict__ cw3, const float* __restrict__ cb3) {
    __shared__ float w[DFF*3];
    int tid = threadIdx.x;               // 256
    for (int j = tid; j < DFF*3; j += 256) w[j] = cw3[j];
    __syncthreads();
    int warp = tid >> 5, lane = tid & 31;
    size_t row = (size_t)blockIdx.x * 8 + warp;
    const float* h = g_H2 + row * DFF;
    float s0 = 0.f, s1 = 0.f, s2 = 0.f;
    for (int j = lane; j < DFF; j += 32) {
        float v = h[j];
        s0 += v * w[j*3+0];
        s1 += v * w[j*3+1];
        s2 += v * w[j*3+2];
    }
#pragma unroll
    for (int o = 16; o > 0; o >>= 1) {
        s0 += __shfl_down_sync(0xFFFFFFFFu, s0, o);
        s1 += __shfl_down_sync(0xFFFFFFFFu, s1, o);
        s2 += __shfl_down_sync(0xFFFFFFFFu, s2, o);
    }
    if (lane == 0) {
        int bp = (int)(row / Kk);
        int k  = (int)(row % Kk);
        int nc = k >> 2;
        const float* cp = &g_coarse[(bp*NCc + nc)*3];
        g_fine[row*3+0] = s0 + cb3[0] + cp[0];
        g_fine[row*3+1] = s1 + cb3[1] + cp[1];
        g_fine[row*3+2] = s2 + cb3[2] + cp[2];
    }
}

// ---------------- Chamfer per-patch partials ----------------
__global__ void chamfer_kernel() {
    int bp  = blockIdx.x;
    int tid = threadIdx.x;   // 64
    __shared__ float f[Kk][3], g[Kk][3];
    __shared__ float r1[Kk], r2[Kk];
    f[tid][0] = g_fine[(bp*Kk + tid)*3+0];
    f[tid][1] = g_fine[(bp*Kk + tid)*3+1];
    f[tid][2] = g_fine[(bp*Kk + tid)*3+2];
    g[tid][0] = g_gxyz[(bp*Kk + tid)*3+0];
    g[tid][1] = g_gxyz[(bp*Kk + tid)*3+1];
    g[tid][2] = g_gxyz[(bp*Kk + tid)*3+2];
    __syncthreads();
    float fx = f[tid][0], fy = f[tid][1], fz = f[tid][2];
    float gx = g[tid][0], gy = g[tid][1], gz = g[tid][2];
    float m1 = FLT_MAX, m2 = FLT_MAX;
    for (int j = 0; j < Kk; j++) {
        float dx = fx - g[j][0], dy = fy - g[j][1], dz = fz - g[j][2];
        m1 = fminf(m1, dx*dx + dy*dy + dz*dz);
        dx = f[j][0] - gx; dy = f[j][1] - gy; dz = f[j][2] - gz;
        m2 = fminf(m2, dx*dx + dy*dy + dz*dz);
    }
    r1[tid] = m1; r2[tid] = m2;
    __syncthreads();
    for (int s = 32; s > 0; s >>= 1) {
        if (tid < s) { r1[tid] += r1[tid+s]; r2[tid] += r2[tid+s]; }
        __syncthreads();
    }
    if (tid == 0) { g_partial[bp] = r1[0]; g_partial[BP + bp] = r2[0]; }
}

// ---------------- deterministic final reduction ----------------
__global__ void final_kernel(float* __restrict__ out, int out_size) {
    __shared__ float s[256];
    int tid = threadIdx.x;
    float a = 0.f;
    for (int i = tid; i < 2*BP; i += 256) a += g_partial[i];
    s[tid] = a;
    __syncthreads();
    for (int st = 128; st > 0; st >>= 1) {
        if (tid < st) s[tid] += s[tid+st];
        __syncthreads();
    }
    if (tid == 0) {
        float loss = s[0] / (float)ROWS;   // mean1 + mean2, both over ROWS elements
        for (int i = 0; i < out_size; i++) out[i] = loss;
    }
}

// ---------------- host orchestration ----------------
static inline void launch_gemm(const float* A, const float* B, float* C,
                               int M, int N, int Kd,
                               const float* alpha, const float* beta, int relu) {
    dim3 grid((N + BN - 1) / BN, (M + BM - 1) / BM);
    gemm_kernel<<<grid, 256>>>(A, B, C, M, N, Kd, alpha, beta, relu);
}

extern "C" void kernel_launch(void* const* d_in, const int* in_sizes, int n_in,
                              void* d_out, int out_size) {
    const float* xyz  = (const float*)d_in[0];
    const float* feat = (const float*)d_in[1];
    const float* w1   = (const float*)d_in[2];
    const float* b1   = (const float*)d_in[3];
    const float* w2   = (const float*)d_in[4];
    const float* b2   = (const float*)d_in[5];
    const float* w3   = (const float*)d_in[6];
    const float* b3   = (const float*)d_in[7];
    const float* cw1  = (const float*)d_in[8];
    const float* cb1  = (const float*)d_in[9];
    const float* g1   = (const float*)d_in[10];
    const float* be1  = (const float*)d_in[11];
    const float* m1   = (const float*)d_in[12];
    const float* v1   = (const float*)d_in[13];
    const float* cw2  = (const float*)d_in[14];
    const float* cb2  = (const float*)d_in[15];
    const float* g2   = (const float*)d_in[16];
    const float* be2  = (const float*)d_in[17];
    const float* m2   = (const float*)d_in[18];
    const float* v2   = (const float*)d_in[19];
    const float* cw3  = (const float*)d_in[20];
    const float* cb3  = (const float*)d_in[21];

    float *pPF, *pH1m, *pH2m, *pCoarse, *pY0, *pH1, *pH2, *pAB;
    cudaGetSymbolAddress((void**)&pPF,     g_pf);
    cudaGetSymbolAddress((void**)&pH1m,    g_h1m);
    cudaGetSymbolAddress((void**)&pH2m,    g_h2m);
    cudaGetSymbolAddress((void**)&pCoarse, g_coarse);
    cudaGetSymbolAddress((void**)&pY0,     g_Y0);
    cudaGetSymbolAddress((void**)&pH1,     g_H1);
    cudaGetSymbolAddress((void**)&pH2,     g_H2);
    cudaGetSymbolAddress((void**)&pAB,     g_ab);

    prep_kernel<<<1, 1024>>>(g1, be1, m1, v1, cb1, g2, be2, m2, v2, cb2);
    fps_kernel<<<Bb, 1024>>>(xyz);
    group_kernel<<<BP, 256>>>(xyz, feat);

    // FoldingNet coarse MLP
    launch_gemm(pPF,  w1, pH1m,    BP, DFF, Dd,   nullptr, b1, 1);
    launch_gemm(pH1m, w2, pH2m,    BP, DFF, DFF,  nullptr, b2, 1);
    launch_gemm(pH2m, w3, pCoarse, BP, 3*NCc, DFF, nullptr, b3, 0);

    // Y0 = pf @ cw1[:128,:]
    launch_gemm(pPF, cw1, pY0, BP, DFF, Dd, nullptr, nullptr, 0);

    // h1 rows (folds seed/pts/bias/BN into elementwise build)
    h1_build_kernel<<<BP, 256>>>(cw1);

    // h2 = relu(bn(h1 @ cw2 + cb2)): the dominant 275 GF GEMM
    launch_gemm(pH1, cw2, pH2, ROWS, DFF, DFF, pAB + 2*DFF, pAB + 3*DFF, 1);

    // fine points + Chamfer
    fine_kernel<<<ROWS/8, 256>>>(cw3, cb3);
    chamfer_kernel<<<BP, Kk>>>();
    final_kernel<<<1, 256>>>((float*)d_out, out_size);
}

// round 4
// speedup vs baseline: 2.8547x; 2.8547x over previous
#include <cuda_runtime.h>
#include <cuda_bf16.h>
#include <math.h>
#include <float.h>
#include <stdint.h>

// ---------------- problem constants ----------------
#define Bb   8
#define Nn   4096
#define Dd   128
#define Pp   256
#define Kk   64
#define DFF  1024
#define NCc  16
#define BP   (Bb*Pp)            // 2048 patches
#define ROWS (BP*Kk)            // 131072 fine rows
#define EPSX 1e-5f

// ---------------- scratch (__device__ globals; no allocation allowed) ----------------
__device__ float g_pcx[BP*3];
__device__ float g_pf[BP*Dd];                    // patch features (maxpooled)  [2048,128]
__device__ float g_gxyz[BP*Kk*3];                // grouped_xyz_norm            [2048,64,3]
__device__ float g_h1m[BP*DFF];                  // MLP hidden 1                [2048,1024]
__device__ float g_h2m[BP*DFF];                  // MLP hidden 2                [2048,1024]
__device__ float g_coarse[BP*NCc*3];             // coarse points               [2048,16,3]
__device__ float g_Y0[BP*DFF];                   // pf @ cw1[:128]              [2048,1024]
__device__ __nv_bfloat16 g_Ah[(size_t)ROWS*DFF]; // h1 hi                       [131072,1024]
__device__ __nv_bfloat16 g_Al[(size_t)ROWS*DFF]; // h1 lo
__device__ __nv_bfloat16 g_BhT[DFF*DFF];         // cw2^T hi  [n,k]
__device__ __nv_bfloat16 g_BlT[DFF*DFF];         // cw2^T lo
__device__ float g_H2[(size_t)ROWS*DFF];         // h2                          [131072,1024]
__device__ float g_fine[ROWS*3];                 // fine points                 [131072,3]
__device__ float g_ab[4*DFF];                    // alpha1,beta1,alpha2,beta2
__device__ float g_partial[2*BP];                // chamfer partial sums

// ---------------- PTX helpers ----------------
static __device__ __forceinline__ uint32_t smem_u32(const void* p) {
    uint32_t a;
    asm("{ .reg .u64 t; cvta.to.shared.u64 t, %1; cvt.u32.u64 %0, t; }" : "=r"(a) : "l"(p));
    return a;
}
static __device__ __forceinline__ void cp16(uint32_t dst, const void* src) {
    asm volatile("cp.async.cg.shared.global [%0], [%1], 16;" :: "r"(dst), "l"(src));
}
#define CP_COMMIT()  asm volatile("cp.async.commit_group;" ::: "memory")
#define CP_WAIT(n)   asm volatile("cp.async.wait_group %0;" :: "n"(n) : "memory")

static __device__ __forceinline__ void ldsm_x4(uint32_t* r, uint32_t addr) {
    asm volatile("ldmatrix.sync.aligned.m8n8.x4.shared.b16 {%0,%1,%2,%3}, [%4];"
                 : "=r"(r[0]), "=r"(r[1]), "=r"(r[2]), "=r"(r[3]) : "r"(addr));
}
static __device__ __forceinline__ void ldsm_x2(uint32_t* r, uint32_t addr) {
    asm volatile("ldmatrix.sync.aligned.m8n8.x2.shared.b16 {%0,%1}, [%2];"
                 : "=r"(r[0]), "=r"(r[1]) : "r"(addr));
}
static __device__ __forceinline__ void mma16816(float* c, const uint32_t* a, const uint32_t* b) {
    asm volatile("mma.sync.aligned.m16n8k16.row.col.f32.bf16.bf16.f32 "
                 "{%0,%1,%2,%3}, {%4,%5,%6,%7}, {%8,%9}, {%0,%1,%2,%3};"
                 : "+f"(c[0]), "+f"(c[1]), "+f"(c[2]), "+f"(c[3])
                 : "r"(a[0]), "r"(a[1]), "r"(a[2]), "r"(a[3]), "r"(b[0]), "r"(b[1]));
}
#define SWZ(off) ((off) ^ (((off) >> 3) & 0x70))

// ---------------- BN fold precompute ----------------
__global__ void prep_kernel(const float* __restrict__ g1, const float* __restrict__ be1,
                            const float* __restrict__ m1, const float* __restrict__ v1,
                            const float* __restrict__ cb1,
                            const float* __restrict__ g2, const float* __restrict__ be2,
                            const float* __restrict__ m2, const float* __restrict__ v2,
                            const float* __restrict__ cb2) {
    int j = blockIdx.x * blockDim.x + threadIdx.x;
    if (j < DFF) {
        float a1 = g1[j] * rsqrtf(v1[j] + EPSX);
        g_ab[j]          = a1;
        g_ab[DFF + j]    = (cb1[j] - m1[j]) * a1 + be1[j];
        float a2 = g2[j] * rsqrtf(v2[j] + EPSX);
        g_ab[2*DFF + j]  = a2;
        g_ab[3*DFF + j]  = (cb2[j] - m2[j]) * a2 + be2[j];
    }
}

// ---------------- split cw2 into transposed bf16 hi/lo ----------------
__global__ void split_w_kernel(const float* __restrict__ cw2) {
    __shared__ float t[32][33];
    int bx = blockIdx.x, by = blockIdx.y;
    int tx = threadIdx.x, ty = threadIdx.y;
    int k = by*32 + ty, n = bx*32 + tx;
    t[ty][tx] = cw2[(size_t)k*DFF + n];
    __syncthreads();
    int nn = bx*32 + ty, kk = by*32 + tx;
    float v = t[tx][ty];
    __nv_bfloat16 h = __float2bfloat16_rn(v);
    g_BhT[(size_t)nn*DFF + kk] = h;
    g_BlT[(size_t)nn*DFF + kk] = __float2bfloat16_rn(v - __bfloat162float(h));
}

// ---------------- FPS (matches JAX argmax semantics bit-exactly) ----------------
__global__ void fps_kernel(const float* __restrict__ xyz) {
    int b = blockIdx.x;
    const float* X = xyz + (size_t)b * Nn * 3;
    __shared__ float mind[Nn];
    __shared__ float rv[1024];
    __shared__ int   ri[1024];
    __shared__ int   s_last;
    int tid = threadIdx.x;

    float px[4], py[4], pz[4];
#pragma unroll
    for (int i = 0; i < 4; i++) {
        int n = tid + i * 1024;
        px[i] = X[n*3+0]; py[i] = X[n*3+1]; pz[i] = X[n*3+2];
        mind[n] = 1e10f;
    }
    if (tid == 0) {
        s_last = 0;
        g_pcx[(b*Pp)*3+0] = X[0];
        g_pcx[(b*Pp)*3+1] = X[1];
        g_pcx[(b*Pp)*3+2] = X[2];
    }
    __syncthreads();

    for (int it = 1; it < Pp; it++) {
        int last = s_last;
        float lx = X[last*3+0], ly = X[last*3+1], lz = X[last*3+2];
        float bv = -1.0f; int bi = Nn;
#pragma unroll
        for (int i = 0; i < 4; i++) {
            int n = tid + i * 1024;
            float dx = __fsub_rn(px[i], lx);
            float dy = __fsub_rn(py[i], ly);
            float dz = __fsub_rn(pz[i], lz);
            float d  = __fadd_rn(__fadd_rn(__fmul_rn(dx,dx), __fmul_rn(dy,dy)), __fmul_rn(dz,dz));
            float m  = fminf(mind[n], d);
            mind[n]  = m;
            if (m > bv || (m == bv && n < bi)) { bv = m; bi = n; }
        }
        rv[tid] = bv; ri[tid] = bi;
        __syncthreads();
        for (int s = 512; s > 0; s >>= 1) {
            if (tid < s) {
                float v2 = rv[tid+s]; int i2 = ri[tid+s];
                if (v2 > rv[tid] || (v2 == rv[tid] && i2 < ri[tid])) { rv[tid] = v2; ri[tid] = i2; }
            }
            __syncthreads();
        }
        if (tid == 0) {
            int w = ri[0];
            s_last = w;
            g_pcx[(b*Pp + it)*3+0] = X[w*3+0];
            g_pcx[(b*Pp + it)*3+1] = X[w*3+1];
            g_pcx[(b*Pp + it)*3+2] = X[w*3+2];
        }
        __syncthreads();
    }
}

// ---------------- kNN grouping + feature maxpool + normalized xyz ----------------
__global__ void group_kernel(const float* __restrict__ xyz, const float* __restrict__ feat) {
    int bp = blockIdx.x;
    int b  = bp / Pp;
    const float* X = xyz + (size_t)b * Nn * 3;
    __shared__ float sd[Nn];
    __shared__ float rv[256];
    __shared__ int   ri[256];
    __shared__ int   sel[Kk];
    int tid = threadIdx.x;

    float cx = g_pcx[bp*3+0], cy = g_pcx[bp*3+1], cz = g_pcx[bp*3+2];
    for (int n = tid; n < Nn; n += 256) {
        float dx = X[n*3+0] - cx, dy = X[n*3+1] - cy, dz = X[n*3+2] - cz;
        sd[n] = dx*dx + dy*dy + dz*dz;
    }
    __syncthreads();

    for (int k = 0; k < Kk; k++) {
        float bv = FLT_MAX; int bi = Nn;
        for (int n = tid; n < Nn; n += 256) {
            float v = sd[n];
            if (v < bv || (v == bv && n < bi)) { bv = v; bi = n; }
        }
        rv[tid] = bv; ri[tid] = bi;
        __syncthreads();
        for (int s = 128; s > 0; s >>= 1) {
            if (tid < s) {
                float v2 = rv[tid+s]; int i2 = ri[tid+s];
                if (v2 < rv[tid] || (v2 == rv[tid] && i2 < ri[tid])) { rv[tid] = v2; ri[tid] = i2; }
            }
            __syncthreads();
        }
        if (tid == 0) { sel[k] = ri[0]; sd[ri[0]] = FLT_MAX; }
        __syncthreads();
    }

    if (tid < Kk) {
        int idx = sel[tid];
        g_gxyz[(bp*Kk + tid)*3+0] = X[idx*3+0] - cx;
        g_gxyz[(bp*Kk + tid)*3+1] = X[idx*3+1] - cy;
        g_gxyz[(bp*Kk + tid)*3+2] = X[idx*3+2] - cz;
    }
    __syncthreads();

    const float* F = feat + (size_t)b * Nn * Dd;
    for (int d = tid; d < Dd; d += 256) {
        float m = -FLT_MAX;
        for (int k = 0; k < Kk; k++)
            m = fmaxf(m, F[(size_t)sel[k] * Dd + d]);
        g_pf[bp*Dd + d] = m;
    }
}

// ---------------- generic fp32 tiled GEMM (small matrices only) ----------------
#define BM 128
#define BN 128
#define BKg 8
#define TM 8
#define TN 8
__global__ void gemm_kernel(const float* __restrict__ A, const float* __restrict__ B,
                            float* __restrict__ C, int M, int N, int Kd,
                            const float* __restrict__ bias, int relu) {
    __shared__ float As[BKg][BM];
    __shared__ float Bs[BKg][BN];
    int tid = threadIdx.x;
    int tx = tid % 16, ty = tid / 16;
    int rowBase = blockIdx.y * BM;
    int colBase = blockIdx.x * BN;

    float acc[TM][TN];
#pragma unroll
    for (int i = 0; i < TM; i++)
#pragma unroll
        for (int j = 0; j < TN; j++) acc[i][j] = 0.0f;

    int aRow  = tid >> 1;
    int aCol4 = (tid & 1) * 4;
    int bRow  = tid >> 5;
    int bCol4 = (tid & 31) * 4;

    for (int k0 = 0; k0 < Kd; k0 += BKg) {
        {
            int gr = rowBase + aRow;
#pragma unroll
            for (int i = 0; i < 4; i++) {
                int gk = k0 + aCol4 + i;
                float v = (gr < M && gk < Kd) ? A[(size_t)gr * Kd + gk] : 0.0f;
                As[aCol4 + i][aRow] = v;
            }
        }
        {
            int gk = k0 + bRow;
#pragma unroll
            for (int i = 0; i < 4; i++) {
                int gc = colBase + bCol4 + i;
                float v = (gk < Kd && gc < N) ? B[(size_t)gk * N + gc] : 0.0f;
                Bs[bRow][bCol4 + i] = v;
            }
        }
        __syncthreads();
#pragma unroll
        for (int kk = 0; kk < BKg; kk++) {
            float a[TM], bb[TN];
#pragma unroll
            for (int i = 0; i < TM; i++) a[i] = As[kk][ty*TM + i];
#pragma unroll
            for (int j = 0; j < TN; j++) bb[j] = Bs[kk][tx*TN + j];
#pragma unroll
            for (int i = 0; i < TM; i++)
#pragma unroll
                for (int j = 0; j < TN; j++) acc[i][j] += a[i] * bb[j];
        }
        __syncthreads();
    }

#pragma unroll
    for (int i = 0; i < TM; i++) {
        int r = rowBase + ty*TM + i;
        if (r >= M) continue;
#pragma unroll
        for (int j = 0; j < TN; j++) {
            int c = colBase + tx*TN + j;
            if (c >= N) continue;
            float v = acc[i][j];
            if (bias) v += bias[c];
            if (relu) v = fmaxf(v, 0.0f);
            C[(size_t)r * N + c] = v;
        }
    }
}

// ---------------- build h1 rows -> split bf16 ----------------
__global__ void h1_build_kernel(const float* __restrict__ cw1) {
    int bp  = blockIdx.x;
    int tid = threadIdx.x;               // 256
    __shared__ float y0[DFF], c0[DFF], c1[DFF], c2[DFF], c3[DFF], c4[DFF], sal[DFF], sbt[DFF];
    __shared__ float crs[NCc*3];

    for (int j = tid; j < DFF; j += 256) {
        y0[j] = g_Y0[(size_t)bp*DFF + j];
        c0[j] = cw1[(size_t)128*DFF + j];
        c1[j] = cw1[(size_t)129*DFF + j];
        c2[j] = cw1[(size_t)130*DFF + j];
        c3[j] = cw1[(size_t)131*DFF + j];
        c4[j] = cw1[(size_t)132*DFF + j];
        sal[j] = g_ab[j];
        sbt[j] = g_ab[DFF + j];
    }
    if (tid < NCc*3) crs[tid] = g_coarse[bp*NCc*3 + tid];
    __syncthreads();

    for (int k = 0; k < Kk; k++) {
        int sidx = k & 3;
        float s0 = (sidx & 1) ?  0.05f : -0.05f;
        float s1 = (sidx & 2) ?  0.05f : -0.05f;
        int nc = k >> 2;
        float pxv = crs[nc*3+0], pyv = crs[nc*3+1], pzv = crs[nc*3+2];
        size_t rowoff = ((size_t)bp * Kk + k) * DFF;
        for (int j = tid; j < DFF; j += 256) {
            float pre = y0[j] + s0*c0[j] + s1*c1[j] + pxv*c2[j] + pyv*c3[j] + pzv*c4[j];
            float act = fmaxf(pre * sal[j] + sbt[j], 0.0f);
            __nv_bfloat16 h = __float2bfloat16_rn(act);
            g_Ah[rowoff + j] = h;
            g_Al[rowoff + j] = __float2bfloat16_rn(act - __bfloat162float(h));
        }
    }
}

// ---------------- mma.sync split-bf16 GEMM: H2 = relu(alpha*(H1@cw2) + beta) ----------------
// CTA tile 128x128, BK=64; K' = 3072 (ah@bh + ah@bl + al@bh) in 48 chunks.
#define GM 128
#define GN 128
#define GKC 64
#define NCHUNK 48
#define SM_ASZ   (GM*128)            // 16384 bytes (128 rows x 128B)
#define SM_BSZ   (GN*128)            // 16384
#define SM_STAGE (SM_ASZ + SM_BSZ)   // 32768
#define SM_TOTAL (2*SM_STAGE)        // 65536

static __device__ __forceinline__ void load_chunk(uint32_t sb, int c, int s, int rowBase, int n0) {
    int kb = c / 3, wh = c - kb*3;
    const __nv_bfloat16* Asrc = (wh < 2) ? g_Ah : g_Al;
    const __nv_bfloat16* Bsrc = (wh == 1) ? g_BlT : g_BhT;
    int gk = kb * GKC;
    uint32_t aBase = sb + s * SM_STAGE;
    uint32_t bBase = aBase + SM_ASZ;
    int tid = threadIdx.x;
#pragma unroll
    for (int i = 0; i < 4; i++) {                 // A: 128 rows x 128B
        int t = tid + i * 256;
        int tr = t >> 3, c8 = t & 7;
        const __nv_bfloat16* src = Asrc + (size_t)(rowBase + tr) * DFF + gk + c8 * 8;
        uint32_t off = tr * 128 + c8 * 16;
        cp16(aBase + SWZ(off), src);
    }
#pragma unroll
    for (int i = 0; i < 4; i++) {                 // B: 128 rows (n) x 128B
        int t = tid + i * 256;
        int nr = t >> 3, c8 = t & 7;
        const __nv_bfloat16* src = Bsrc + (size_t)(n0 + nr) * DFF + gk + c8 * 8;
        uint32_t off = nr * 128 + c8 * 16;
        cp16(bBase + SWZ(off), src);
    }
    CP_COMMIT();
}

__global__ void __launch_bounds__(256) gemm_mma_kernel() {
    extern __shared__ char smem[];
    uint32_t sb = smem_u32(smem);
    int tid  = threadIdx.x;
    int wid  = tid >> 5, lane = tid & 31;
    int rowBase = blockIdx.y * GM;
    int n0      = blockIdx.x * GN;

    // warp tile: 64(M) x 32(N); warps laid out 2(M) x 4(N)
    int wr = (wid & 1) * 64;
    int wc = (wid >> 1) * 32;

    // per-lane ldmatrix addressing components
    int a_row = wr + (lane & 15);
    int a_kb  = (lane >> 4) * 16;            // byte offset within 32B k16-step block
    int b_row = wc + (lane & 7);
    int b_kb  = ((lane >> 3) & 1) * 16;

    float acc[4][4][4];
#pragma unroll
    for (int i = 0; i < 4; i++)
#pragma unroll
        for (int j = 0; j < 4; j++)
#pragma unroll
            for (int q = 0; q < 4; q++) acc[i][j][q] = 0.0f;

    load_chunk(sb, 0, 0, rowBase, n0);
    load_chunk(sb, 1, 1, rowBase, n0);

    for (int c = 0; c < NCHUNK; c++) {
        int s = c & 1;
        if (c < NCHUNK - 1) { CP_WAIT(1); } else { CP_WAIT(0); }
        __syncthreads();                       // tile for chunk c visible
        uint32_t aBase = sb + s * SM_STAGE;
        uint32_t bBase = aBase + SM_ASZ;
#pragma unroll
        for (int ks = 0; ks < 4; ks++) {
            uint32_t aF[4][4], bF[4][2];
#pragma unroll
            for (int i = 0; i < 4; i++) {
                uint32_t off = (uint32_t)(a_row + i*16) * 128 + ks*32 + a_kb;
                ldsm_x4(aF[i], aBase + SWZ(off));
            }
#pragma unroll
            for (int j = 0; j < 4; j++) {
                uint32_t off = (uint32_t)(b_row + j*8) * 128 + ks*32 + b_kb;
                ldsm_x2(bF[j], bBase + SWZ(off));
            }
#pragma unroll
            for (int i = 0; i < 4; i++)
#pragma unroll
                for (int j = 0; j < 4; j++)
                    mma16816(acc[i][j], aF[i], bF[j]);
        }
        __syncthreads();                       // everyone done reading stage s
        if (c + 2 < NCHUNK) load_chunk(sb, c + 2, s, rowBase, n0);
    }

    // epilogue: relu(acc*alpha + beta) -> g_H2
    const float* alpha = g_ab + 2*DFF;
    const float* beta  = g_ab + 3*DFF;
#pragma unroll
    for (int i = 0; i < 4; i++) {
        int r0 = rowBase + wr + i*16 + (lane >> 2);
#pragma unroll
        for (int j = 0; j < 4; j++) {
            int cix = n0 + wc + j*8 + 2*(lane & 3);
            float al0 = alpha[cix], al1 = alpha[cix+1];
            float bt0 = beta[cix],  bt1 = beta[cix+1];
            float2 v0, v1;
            v0.x = fmaxf(acc[i][j][0]*al0 + bt0, 0.0f);
            v0.y = fmaxf(acc[i][j][1]*al1 + bt1, 0.0f);
            v1.x = fmaxf(acc[i][j][2]*al0 + bt0, 0.0f);
            v1.y = fmaxf(acc[i][j][3]*al1 + bt1, 0.0f);
            *(float2*)&g_H2[(size_t)r0      * DFF + cix] = v0;
            *(float2*)&g_H2[(size_t)(r0+8) * DFF + cix] = v1;
        }
    }
}

// ---------------- fine = H2 @ cw3 + cb3 + pts  (one warp per row) ----------------
__global__ void fine_kernel(const float* __restrict__ cw3, const float* __restrict__ cb3) {
    __shared__ float w[DFF*3];
    int tid = threadIdx.x;               // 256
    for (int j = tid; j < DFF*3; j += 256) w[j] = cw3[j];
    __syncthreads();
    int warp = tid >> 5, lane = tid & 31;
    size_t row = (size_t)blockIdx.x * 8 + warp;
    const float* h = g_H2 + row * DFF;
    float s0 = 0.f, s1 = 0.f, s2 = 0.f;
    for (int j = lane; j < DFF; j += 32) {
        float v = h[j];
        s0 += v * w[j*3+0];
        s1 += v * w[j*3+1];
        s2 += v * w[j*3+2];
    }
#pragma unroll
    for (int o = 16; o > 0; o >>= 1) {
        s0 += __shfl_down_sync(0xFFFFFFFFu, s0, o);
        s1 += __shfl_down_sync(0xFFFFFFFFu, s1, o);
        s2 += __shfl_down_sync(0xFFFFFFFFu, s2, o);
    }
    if (lane == 0) {
        int bp = (int)(row / Kk);
        int k  = (int)(row % Kk);
        int nc = k >> 2;
        const float* cp = &g_coarse[(bp*NCc + nc)*3];
        g_fine[row*3+0] = s0 + cb3[0] + cp[0];
        g_fine[row*3+1] = s1 + cb3[1] + cp[1];
        g_fine[row*3+2] = s2 + cb3[2] + cp[2];
    }
}

// ---------------- Chamfer per-patch partials ----------------
__global__ void chamfer_kernel() {
    int bp  = blockIdx.x;
    int tid = threadIdx.x;   // 64
    __shared__ float f[Kk][3], g[Kk][3];
    __shared__ float r1[Kk], r2[Kk];
    f[tid][0] = g_fine[(bp*Kk + tid)*3+0];
    f[tid][1] = g_fine[(bp*Kk + tid)*3+1];
    f[tid][2] = g_fine[(bp*Kk + tid)*3+2];
    g[tid][0] = g_gxyz[(bp*Kk + tid)*3+0];
    g[tid][1] = g_gxyz[(bp*Kk + tid)*3+1];
    g[tid][2] = g_gxyz[(bp*Kk + tid)*3+2];
    __syncthreads();
    float fx = f[tid][0], fy = f[tid][1], fz = f[tid][2];
    float gx = g[tid][0], gy = g[tid][1], gz = g[tid][2];
    float m1 = FLT_MAX, m2 = FLT_MAX;
    for (int j = 0; j < Kk; j++) {
        float dx = fx - g[j][0], dy = fy - g[j][1], dz = fz - g[j][2];
        m1 = fminf(m1, dx*dx + dy*dy + dz*dz);
        dx = f[j][0] - gx; dy = f[j][1] - gy; dz = f[j][2] - gz;
        m2 = fminf(m2, dx*dx + dy*dy + dz*dz);
    }
    r1[tid] = m1; r2[tid] = m2;
    __syncthreads();
    for (int s = 32; s > 0; s >>= 1) {
        if (tid < s) { r1[tid] += r1[tid+s]; r2[tid] += r2[tid+s]; }
        __syncthreads();
    }
    if (tid == 0) { g_partial[bp] = r1[0]; g_partial[BP + bp] = r2[0]; }
}

// ---------------- deterministic final reduction ----------------
__global__ void final_kernel(float* __restrict__ out, int out_size) {
    __shared__ float s[256];
    int tid = threadIdx.x;
    float a = 0.f;
    for (int i = tid; i < 2*BP; i += 256) a += g_partial[i];
    s[tid] = a;
    __syncthreads();
    for (int st = 128; st > 0; st >>= 1) {
        if (tid < st) s[tid] += s[tid+st];
        __syncthreads();
    }
    if (tid == 0) {
        float loss = s[0] / (float)ROWS;
        for (int i = 0; i < out_size; i++) out[i] = loss;
    }
}

// ---------------- host orchestration ----------------
static inline void launch_gemm(const float* A, const float* B, float* C,
                               int M, int N, int Kd, const float* bias, int relu) {
    dim3 grid((N + BN - 1) / BN, (M + BM - 1) / BM);
    gemm_kernel<<<grid, 256>>>(A, B, C, M, N, Kd, bias, relu);
}

extern "C" void kernel_launch(void* const* d_in, const int* in_sizes, int n_in,
                              void* d_out, int out_size) {
    const float* xyz  = (const float*)d_in[0];
    const float* feat = (const float*)d_in[1];
    const float* w1   = (const float*)d_in[2];
    const float* b1   = (const float*)d_in[3];
    const float* w2   = (const float*)d_in[4];
    const float* b2   = (const float*)d_in[5];
    const float* w3   = (const float*)d_in[6];
    const float* b3   = (const float*)d_in[7];
    const float* cw1  = (const float*)d_in[8];
    const float* cb1  = (const float*)d_in[9];
    const float* g1   = (const float*)d_in[10];
    const float* be1  = (const float*)d_in[11];
    const float* m1   = (const float*)d_in[12];
    const float* v1   = (const float*)d_in[13];
    const float* cw2  = (const float*)d_in[14];
    const float* cb2  = (const float*)d_in[15];
    const float* g2   = (const float*)d_in[16];
    const float* be2  = (const float*)d_in[17];
    const float* m2   = (const float*)d_in[18];
    const float* v2   = (const float*)d_in[19];
    const float* cw3  = (const float*)d_in[20];
    const float* cb3  = (const float*)d_in[21];

    float *pPF, *pH1m, *pH2m, *pCoarse, *pY0;
    cudaGetSymbolAddress((void**)&pPF,     g_pf);
    cudaGetSymbolAddress((void**)&pH1m,    g_h1m);
    cudaGetSymbolAddress((void**)&pH2m,    g_h2m);
    cudaGetSymbolAddress((void**)&pCoarse, g_coarse);
    cudaGetSymbolAddress((void**)&pY0,     g_Y0);

    static int smem_set = 0;
    if (!smem_set) {
        cudaFuncSetAttribute(gemm_mma_kernel, cudaFuncAttributeMaxDynamicSharedMemorySize, SM_TOTAL);
        smem_set = 1;
    }

    prep_kernel<<<1, 1024>>>(g1, be1, m1, v1, cb1, g2, be2, m2, v2, cb2);
    split_w_kernel<<<dim3(32, 32), dim3(32, 32)>>>(cw2);
    fps_kernel<<<Bb, 1024>>>(xyz);
    group_kernel<<<BP, 256>>>(xyz, feat);

    // FoldingNet coarse MLP (small fp32 GEMMs)
    launch_gemm(pPF,  w1, pH1m,    BP, DFF,   Dd,  b1, 1);
    launch_gemm(pH1m, w2, pH2m,    BP, DFF,   DFF, b2, 1);
    launch_gemm(pH2m, w3, pCoarse, BP, 3*NCc, DFF, b3, 0);

    // Y0 = pf @ cw1[:128,:]
    launch_gemm(pPF, cw1, pY0, BP, DFF, Dd, nullptr, 0);

    // h1 rows -> split bf16 (folds seed/pts/bias/BN into elementwise build)
    h1_build_kernel<<<BP, 256>>>(cw1);

    // h2 = relu(bn(h1 @ cw2 + cb2)): split-bf16 mma.sync GEMM
    gemm_mma_kernel<<<dim3(DFF/GN, ROWS/GM), 256, SM_TOTAL>>>();

    // fine points + Chamfer
    fine_kernel<<<ROWS/8, 256>>>(cw3, cb3);
    chamfer_kernel<<<BP, Kk>>>();
    final_kernel<<<1, 256>>>((float*)d_out, out_size);
}

// round 5
// speedup vs baseline: 3.6778x; 1.2883x over previous
#include <cuda_runtime.h>
#include <cuda_bf16.h>
#include <math.h>
#include <float.h>
#include <stdint.h>

// ---------------- problem constants ----------------
#define Bb   8
#define Nn   4096
#define Dd   128
#define Pp   256
#define Kk   64
#define DFF  1024
#define NCc  16
#define BP   (Bb*Pp)            // 2048 patches
#define ROWS (BP*Kk)            // 131072 fine rows
#define EPSX 1e-5f

// ---------------- scratch (__device__ globals; no allocation allowed) ----------------
__device__ float g_pcx[BP*3];
__device__ float g_pf[BP*Dd];
__device__ float g_gxyz[BP*Kk*3];
__device__ float g_h2m[BP*DFF];
__device__ float g_coarse[BP*NCc*3];
__device__ float g_Y0[BP*DFF];
__device__ __nv_bfloat16 g_Ah[(size_t)ROWS*DFF];   // h1 hi
__device__ __nv_bfloat16 g_Al[(size_t)ROWS*DFF];   // h1 lo
__device__ __nv_bfloat16 g_BhT[DFF*DFF];           // cw2^T hi [n,k]
__device__ __nv_bfloat16 g_BlT[DFF*DFF];           // cw2^T lo
__device__ __nv_bfloat16 g_W2hT[DFF*DFF];          // w2^T hi
__device__ __nv_bfloat16 g_W2lT[DFF*DFF];          // w2^T lo
__device__ __nv_bfloat16 g_MAh[BP*DFF];            // h1m hi (MLP)
__device__ __nv_bfloat16 g_MAl[BP*DFF];            // h1m lo
__device__ float g_finepart[(size_t)8*ROWS*3];     // per-n-slice fine partials
__device__ float g_fine[ROWS*3];
__device__ float g_ab[4*DFF];
__device__ float g_partial[2*BP];

// ---------------- PTX helpers ----------------
static __device__ __forceinline__ uint32_t smem_u32(const void* p) {
    uint32_t a;
    asm("{ .reg .u64 t; cvta.to.shared.u64 t, %1; cvt.u32.u64 %0, t; }" : "=r"(a) : "l"(p));
    return a;
}
static __device__ __forceinline__ void cp16(uint32_t dst, const void* src) {
    asm volatile("cp.async.cg.shared.global [%0], [%1], 16;" :: "r"(dst), "l"(src));
}
#define CP_COMMIT()  asm volatile("cp.async.commit_group;" ::: "memory")
#define CP_WAIT(n)   asm volatile("cp.async.wait_group %0;" :: "n"(n) : "memory")

static __device__ __forceinline__ void ldsm_x4(uint32_t* r, uint32_t addr) {
    asm volatile("ldmatrix.sync.aligned.m8n8.x4.shared.b16 {%0,%1,%2,%3}, [%4];"
                 : "=r"(r[0]), "=r"(r[1]), "=r"(r[2]), "=r"(r[3]) : "r"(addr));
}
static __device__ __forceinline__ void ldsm_x2(uint32_t* r, uint32_t addr) {
    asm volatile("ldmatrix.sync.aligned.m8n8.x2.shared.b16 {%0,%1}, [%2];"
                 : "=r"(r[0]), "=r"(r[1]) : "r"(addr));
}
static __device__ __forceinline__ void mma16816(float* c, const uint32_t* a, const uint32_t* b) {
    asm volatile("mma.sync.aligned.m16n8k16.row.col.f32.bf16.bf16.f32 "
                 "{%0,%1,%2,%3}, {%4,%5,%6,%7}, {%8,%9}, {%0,%1,%2,%3};"
                 : "+f"(c[0]), "+f"(c[1]), "+f"(c[2]), "+f"(c[3])
                 : "r"(a[0]), "r"(a[1]), "r"(a[2]), "r"(a[3]), "r"(b[0]), "r"(b[1]));
}
#define SWZ(off) ((off) ^ (((off) >> 3) & 0x70))

// ---------------- BN fold precompute ----------------
__global__ void prep_kernel(const float* __restrict__ g1, const float* __restrict__ be1,
                            const float* __restrict__ m1, const float* __restrict__ v1,
                            const float* __restrict__ cb1,
                            const float* __restrict__ g2, const float* __restrict__ be2,
                            const float* __restrict__ m2, const float* __restrict__ v2,
                            const float* __restrict__ cb2) {
    int j = blockIdx.x * blockDim.x + threadIdx.x;
    if (j < DFF) {
        float a1 = g1[j] * rsqrtf(v1[j] + EPSX);
        g_ab[j]          = a1;
        g_ab[DFF + j]    = (cb1[j] - m1[j]) * a1 + be1[j];
        float a2 = g2[j] * rsqrtf(v2[j] + EPSX);
        g_ab[2*DFF + j]  = a2;
        g_ab[3*DFF + j]  = (cb2[j] - m2[j]) * a2 + be2[j];
    }
}

// ---------------- split a [DFF,DFF] fp32 weight into transposed bf16 hi/lo ----------------
__global__ void split_w_kernel(const float* __restrict__ W,
                               __nv_bfloat16* __restrict__ outH,
                               __nv_bfloat16* __restrict__ outL) {
    __shared__ float t[32][33];
    int bx = blockIdx.x, by = blockIdx.y;
    int tx = threadIdx.x, ty = threadIdx.y;
    int k = by*32 + ty, n = bx*32 + tx;
    t[ty][tx] = W[(size_t)k*DFF + n];
    __syncthreads();
    int nn = bx*32 + ty, kk = by*32 + tx;
    float v = t[tx][ty];
    __nv_bfloat16 h = __float2bfloat16_rn(v);
    outH[(size_t)nn*DFF + kk] = h;
    outL[(size_t)nn*DFF + kk] = __float2bfloat16_rn(v - __bfloat162float(h));
}

// ---------------- FPS (matches JAX argmax semantics; register mind + shuffle reduce) ----------------
__global__ void fps_kernel(const float* __restrict__ xyz) {
    int b = blockIdx.x;
    const float* X = xyz + (size_t)b * Nn * 3;
    __shared__ unsigned long long wb[32];
    __shared__ unsigned long long swin;
    int tid = threadIdx.x;
    int warp = tid >> 5, lane = tid & 31;

    float px[4], py[4], pz[4], mind[4];
#pragma unroll
    for (int i = 0; i < 4; i++) {
        int n = tid + i * 1024;
        px[i] = X[n*3+0]; py[i] = X[n*3+1]; pz[i] = X[n*3+2];
        mind[i] = 1e10f;
    }
    if (tid == 0) {
        g_pcx[(b*Pp)*3+0] = X[0];
        g_pcx[(b*Pp)*3+1] = X[1];
        g_pcx[(b*Pp)*3+2] = X[2];
        swin = 0;   // index 0
    }
    __syncthreads();

    float lx = X[0], ly = X[1], lz = X[2];
    for (int it = 1; it < Pp; it++) {
        unsigned long long key = 0;
#pragma unroll
        for (int i = 0; i < 4; i++) {
            int n = tid + i * 1024;
            // exact JAX order: ((dx*dx + dy*dy) + dz*dz), no FMA contraction
            float dx = __fsub_rn(px[i], lx);
            float dy = __fsub_rn(py[i], ly);
            float dz = __fsub_rn(pz[i], lz);
            float d  = __fadd_rn(__fadd_rn(__fmul_rn(dx,dx), __fmul_rn(dy,dy)), __fmul_rn(dz,dz));
            float m  = fminf(mind[i], d);
            mind[i]  = m;
            // lexicographic max: (dist, then lower n). n <= 4095.
            unsigned long long kk2 = ((unsigned long long)__float_as_uint(m) << 32)
                                   | (unsigned long long)(uint32_t)(4095 - n);
            if (kk2 > key) key = kk2;
        }
#pragma unroll
        for (int o = 16; o > 0; o >>= 1) {
            unsigned long long v = __shfl_down_sync(0xFFFFFFFFu, key, o);
            if (v > key) key = v;
        }
        if (lane == 0) wb[warp] = key;
        __syncthreads();
        if (warp == 0) {
            unsigned long long k2 = wb[lane];
#pragma unroll
            for (int o = 16; o > 0; o >>= 1) {
                unsigned long long v = __shfl_down_sync(0xFFFFFFFFu, k2, o);
                if (v > k2) k2 = v;
            }
            if (lane == 0) swin = k2;
        }
        __syncthreads();
        int w = 4095 - (int)(swin & 0xFFFFFFFFu);
        lx = X[w*3+0]; ly = X[w*3+1]; lz = X[w*3+2];
        if (tid == 0) {
            g_pcx[(b*Pp + it)*3+0] = lx;
            g_pcx[(b*Pp + it)*3+1] = ly;
            g_pcx[(b*Pp + it)*3+2] = lz;
        }
    }
}

// ---------------- kNN grouping (register candidates + u64 shuffle argmin) ----------------
__global__ void group_kernel(const float* __restrict__ xyz, const float* __restrict__ feat) {
    int bp = blockIdx.x;
    int b  = bp / Pp;
    const float* X = xyz + (size_t)b * Nn * 3;
    __shared__ unsigned long long wb[8];
    __shared__ unsigned long long swin;
    __shared__ int sel[Kk];
    __shared__ float mx[2][Dd];
    int tid = threadIdx.x;
    int warp = tid >> 5, lane = tid & 31;

    float cx = g_pcx[bp*3+0], cy = g_pcx[bp*3+1], cz = g_pcx[bp*3+2];
    float d[16];
#pragma unroll
    for (int j = 0; j < 16; j++) {
        int n = tid + j * 256;
        float dx = X[n*3+0] - cx, dy = X[n*3+1] - cy, dz = X[n*3+2] - cz;
        d[j] = dx*dx + dy*dy + dz*dz;
    }

    for (int k = 0; k < Kk; k++) {
        float bd = FLT_MAX; int bj = 0;
#pragma unroll
        for (int j = 0; j < 16; j++)
            if (d[j] < bd) { bd = d[j]; bj = j; }   // strict < keeps lowest j (lowest idx)
        unsigned long long key = ((unsigned long long)__float_as_uint(bd) << 32)
                               | (unsigned long long)(uint32_t)(tid + bj*256);
#pragma unroll
        for (int o = 16; o > 0; o >>= 1) {
            unsigned long long v = __shfl_down_sync(0xFFFFFFFFu, key, o);
            if (v < key) key = v;
        }
        if (lane == 0) wb[warp] = key;
        __syncthreads();
        if (warp == 0) {
            unsigned long long k2 = (lane < 8) ? wb[lane] : 0xFFFFFFFFFFFFFFFFull;
#pragma unroll
            for (int o = 4; o > 0; o >>= 1) {
                unsigned long long v = __shfl_down_sync(0xFFFFFFFFu, k2, o);
                if (v < k2) k2 = v;
            }
            if (lane == 0) swin = k2;
        }
        __syncthreads();
        int widx = (int)(swin & 0xFFFFFFFFu);
        if (tid == 0) sel[k] = widx;
        if ((widx & 255) == tid) {
            int jw = widx >> 8;
#pragma unroll
            for (int j = 0; j < 16; j++)
                if (j == jw) d[j] = FLT_MAX;
        }
        __syncthreads();
    }

    if (tid < Kk) {
        int idx = sel[tid];
        g_gxyz[(bp*Kk + tid)*3+0] = X[idx*3+0] - cx;
        g_gxyz[(bp*Kk + tid)*3+1] = X[idx*3+1] - cy;
        g_gxyz[(bp*Kk + tid)*3+2] = X[idx*3+2] - cz;
    }
    __syncthreads();

    // maxpool: 2 thread-halves over k, combined via smem
    const float* F = feat + (size_t)b * Nn * Dd;
    int half = tid >> 7, dd2 = tid & 127;
    float m = -FLT_MAX;
#pragma unroll 4
    for (int k = half*32; k < half*32 + 32; k++)
        m = fmaxf(m, F[(size_t)sel[k] * Dd + dd2]);
    mx[half][dd2] = m;
    __syncthreads();
    if (half == 0)
        g_pf[bp*Dd + dd2] = fmaxf(mx[0][dd2], mx[1][dd2]);
}

// ---------------- generic fp32 tiled GEMM (small matrices; optional split-bf16 out) ----------------
#define BM 128
#define BN 128
#define BKg 8
#define TM 8
#define TN 8
__global__ void gemm_kernel(const float* __restrict__ A, const float* __restrict__ B,
                            float* __restrict__ C, int M, int N, int Kd,
                            const float* __restrict__ bias, int relu,
                            __nv_bfloat16* __restrict__ outH, __nv_bfloat16* __restrict__ outL) {
    __shared__ float As[BKg][BM];
    __shared__ float Bs[BKg][BN];
    int tid = threadIdx.x;
    int tx = tid % 16, ty = tid / 16;
    int rowBase = blockIdx.y * BM;
    int colBase = blockIdx.x * BN;

    float acc[TM][TN];
#pragma unroll
    for (int i = 0; i < TM; i++)
#pragma unroll
        for (int j = 0; j < TN; j++) acc[i][j] = 0.0f;

    int aRow  = tid >> 1;
    int aCol4 = (tid & 1) * 4;
    int bRow  = tid >> 5;
    int bCol4 = (tid & 31) * 4;

    for (int k0 = 0; k0 < Kd; k0 += BKg) {
        {
            int gr = rowBase + aRow;
#pragma unroll
            for (int i = 0; i < 4; i++) {
                int gk = k0 + aCol4 + i;
                float v = (gr < M && gk < Kd) ? A[(size_t)gr * Kd + gk] : 0.0f;
                As[aCol4 + i][aRow] = v;
            }
        }
        {
            int gk = k0 + bRow;
#pragma unroll
            for (int i = 0; i < 4; i++) {
                int gc = colBase + bCol4 + i;
                float v = (gk < Kd && gc < N) ? B[(size_t)gk * N + gc] : 0.0f;
                Bs[bRow][bCol4 + i] = v;
            }
        }
        __syncthreads();
#pragma unroll
        for (int kk = 0; kk < BKg; kk++) {
            float a[TM], bb[TN];
#pragma unroll
            for (int i = 0; i < TM; i++) a[i] = As[kk][ty*TM + i];
#pragma unroll
            for (int j = 0; j < TN; j++) bb[j] = Bs[kk][tx*TN + j];
#pragma unroll
            for (int i = 0; i < TM; i++)
#pragma unroll
                for (int j = 0; j < TN; j++) acc[i][j] += a[i] * bb[j];
        }
        __syncthreads();
    }

#pragma unroll
    for (int i = 0; i < TM; i++) {
        int r = rowBase + ty*TM + i;
        if (r >= M) continue;
#pragma unroll
        for (int j = 0; j < TN; j++) {
            int c = colBase + tx*TN + j;
            if (c >= N) continue;
            float v = acc[i][j];
            if (bias) v += bias[c];
            if (relu) v = fmaxf(v, 0.0f);
            if (outH) {
                __nv_bfloat16 h = __float2bfloat16_rn(v);
                outH[(size_t)r * N + c] = h;
                outL[(size_t)r * N + c] = __float2bfloat16_rn(v - __bfloat162float(h));
            } else {
                C[(size_t)r * N + c] = v;
            }
        }
    }
}

// ---------------- build h1 rows -> split bf16 ----------------
__global__ void h1_build_kernel(const float* __restrict__ cw1) {
    int bp  = blockIdx.x;
    int tid = threadIdx.x;               // 256
    __shared__ float y0[DFF], c0[DFF], c1[DFF], c2[DFF], c3[DFF], c4[DFF], sal[DFF], sbt[DFF];
    __shared__ float crs[NCc*3];

    for (int j = tid; j < DFF; j += 256) {
        y0[j] = g_Y0[(size_t)bp*DFF + j];
        c0[j] = cw1[(size_t)128*DFF + j];
        c1[j] = cw1[(size_t)129*DFF + j];
        c2[j] = cw1[(size_t)130*DFF + j];
        c3[j] = cw1[(size_t)131*DFF + j];
        c4[j] = cw1[(size_t)132*DFF + j];
        sal[j] = g_ab[j];
        sbt[j] = g_ab[DFF + j];
    }
    if (tid < NCc*3) crs[tid] = g_coarse[bp*NCc*3 + tid];
    __syncthreads();

    int j0 = tid * 4;                    // 4 consecutive columns per thread
    float4 vy = *(float4*)&y0[j0];
    float4 v0 = *(float4*)&c0[j0];
    float4 v1 = *(float4*)&c1[j0];
    float4 v2 = *(float4*)&c2[j0];
    float4 v3 = *(float4*)&c3[j0];
    float4 v4 = *(float4*)&c4[j0];
    float4 va = *(float4*)&sal[j0];
    float4 vb = *(float4*)&sbt[j0];

    for (int k = 0; k < Kk; k++) {
        int sidx = k & 3;
        float s0 = (sidx & 1) ?  0.05f : -0.05f;
        float s1 = (sidx & 2) ?  0.05f : -0.05f;
        int nc = k >> 2;
        float pxv = crs[nc*3+0], pyv = crs[nc*3+1], pzv = crs[nc*3+2];
        size_t rowoff = ((size_t)bp * Kk + k) * DFF + j0;
        uint32_t hpk[2], lpk[2];
        float pre, act, hi;
        __nv_bfloat16 h2[2], l2[2];
#pragma unroll
        for (int q = 0; q < 4; q++) {
            float yy = (&vy.x)[q], w0 = (&v0.x)[q], w1 = (&v1.x)[q],
                  w2 = (&v2.x)[q], w3 = (&v3.x)[q], w4 = (&v4.x)[q],
                  al = (&va.x)[q], bt = (&vb.x)[q];
            pre = yy + s0*w0 + s1*w1 + pxv*w2 + pyv*w3 + pzv*w4;
            act = fmaxf(pre * al + bt, 0.0f);
            __nv_bfloat16 h = __float2bfloat16_rn(act);
            hi  = __bfloat162float(h);
            h2[q & 1] = h;
            l2[q & 1] = __float2bfloat16_rn(act - hi);
            if (q & 1) {
                hpk[q>>1] = ((uint32_t)*(uint16_t*)&h2[1] << 16) | *(uint16_t*)&h2[0];
                lpk[q>>1] = ((uint32_t)*(uint16_t*)&l2[1] << 16) | *(uint16_t*)&l2[0];
            }
        }
        *(uint2*)&g_Ah[rowoff] = make_uint2(hpk[0], hpk[1]);
        *(uint2*)&g_Al[rowoff] = make_uint2(lpk[0], lpk[1]);
    }
}

// ---------------- shared split-bf16 mma mainloop (CTA 128x128, BK=64) ----------------
#define GM 128
#define GN 128
#define SM_ASZ   (GM*128)
#define SM_BSZ   (GN*128)
#define SM_STAGE (SM_ASZ + SM_BSZ)
#define SM_TOTAL (2*SM_STAGE)        // 65536

static __device__ __forceinline__ void load_chunk_p(uint32_t sb, int s,
        const __nv_bfloat16* __restrict__ Asrc, const __nv_bfloat16* __restrict__ Bsrc,
        int gk, int rowBase, int n0) {
    uint32_t aBase = sb + s * SM_STAGE;
    uint32_t bBase = aBase + SM_ASZ;
    int tid = threadIdx.x;
#pragma unroll
    for (int i = 0; i < 4; i++) {
        int t = tid + i * 256;
        int tr = t >> 3, c8 = t & 7;
        const __nv_bfloat16* src = Asrc + (size_t)(rowBase + tr) * DFF + gk + c8 * 8;
        uint32_t off = tr * 128 + c8 * 16;
        cp16(aBase + SWZ(off), src);
    }
#pragma unroll
    for (int i = 0; i < 4; i++) {
        int t = tid + i * 256;
        int nr = t >> 3, c8 = t & 7;
        const __nv_bfloat16* src = Bsrc + (size_t)(n0 + nr) * DFF + gk + c8 * 8;
        uint32_t off = nr * 128 + c8 * 16;
        cp16(bBase + SWZ(off), src);
    }
    CP_COMMIT();
}

static __device__ __forceinline__ void pick_chunk(int c,
        const __nv_bfloat16* Ah, const __nv_bfloat16* Al,
        const __nv_bfloat16* BhT, const __nv_bfloat16* BlT,
        const __nv_bfloat16** As_, const __nv_bfloat16** Bs_, int* gk) {
    int kb = c / 3, wh = c - kb*3;
    *As_ = (wh < 2) ? Ah : Al;
    *Bs_ = (wh == 1) ? BlT : BhT;
    *gk = kb * 64;
}

static __device__ __forceinline__ void mma_mainloop(
        const __nv_bfloat16* __restrict__ Ah, const __nv_bfloat16* __restrict__ Al,
        const __nv_bfloat16* __restrict__ BhT, const __nv_bfloat16* __restrict__ BlT,
        int nchunk, uint32_t sb, int rowBase, int n0, float acc[4][4][4],
        int a_row, int a_kb, int b_row, int b_kb) {
    const __nv_bfloat16 *As_, *Bs_;
    int gk;
    pick_chunk(0, Ah, Al, BhT, BlT, &As_, &Bs_, &gk);
    load_chunk_p(sb, 0, As_, Bs_, gk, rowBase, n0);
    pick_chunk(1, Ah, Al, BhT, BlT, &As_, &Bs_, &gk);
    load_chunk_p(sb, 1, As_, Bs_, gk, rowBase, n0);

    for (int c = 0; c < nchunk; c++) {
        int s = c & 1;
        if (c < nchunk - 1) { CP_WAIT(1); } else { CP_WAIT(0); }
        __syncthreads();
        uint32_t aBase = sb + s * SM_STAGE;
        uint32_t bBase = aBase + SM_ASZ;
#pragma unroll
        for (int ks = 0; ks < 4; ks++) {
            uint32_t aF[4][4], bF[4][2];
#pragma unroll
            for (int i = 0; i < 4; i++) {
                uint32_t off = (uint32_t)(a_row + i*16) * 128 + ks*32 + a_kb;
                ldsm_x4(aF[i], aBase + SWZ(off));
            }
#pragma unroll
            for (int j = 0; j < 4; j++) {
                uint32_t off = (uint32_t)(b_row + j*8) * 128 + ks*32 + b_kb;
                ldsm_x2(bF[j], bBase + SWZ(off));
            }
#pragma unroll
            for (int i = 0; i < 4; i++)
#pragma unroll
                for (int j = 0; j < 4; j++)
                    mma16816(acc[i][j], aF[i], bF[j]);
        }
        __syncthreads();
        if (c + 2 < nchunk) {
            pick_chunk(c + 2, Ah, Al, BhT, BlT, &As_, &Bs_, &gk);
            load_chunk_p(sb, s, As_, Bs_, gk, rowBase, n0);
        }
    }
}

// ---------------- BIG GEMM: h2 = relu(bn(h1@cw2)), fused fine partials (no H2!) ----------------
__global__ void __launch_bounds__(256) gemm_big_kernel(const float* __restrict__ cw3) {
    extern __shared__ char smem[];
    uint32_t sb = smem_u32(smem);
    int tid  = threadIdx.x;
    int wid  = tid >> 5, lane = tid & 31;
    int rowBase = blockIdx.y * GM;
    int n0      = blockIdx.x * GN;

    int wr = (wid & 1) * 64;
    int wc = (wid >> 1) * 32;
    int a_row = wr + (lane & 15);
    int a_kb  = (lane >> 4) * 16;
    int b_row = wc + (lane & 7);
    int b_kb  = ((lane >> 3) & 1) * 16;

    float acc[4][4][4];
#pragma unroll
    for (int i = 0; i < 4; i++)
#pragma unroll
        for (int j = 0; j < 4; j++)
#pragma unroll
            for (int q = 0; q < 4; q++) acc[i][j][q] = 0.0f;

    mma_mainloop(g_Ah, g_Al, g_BhT, g_BlT, 48, sb, rowBase, n0, acc,
                 a_row, a_kb, b_row, b_kb);

    // ---- epilogue: v = relu(acc*alpha+beta); fine partial = v @ cw3[n0:n0+128] ----
    float* w3s  = (float*)smem;                  // [128][3]
    float* part = (float*)(smem + 2048);         // [2][64][4][3]
    if (tid < 128) {
        w3s[tid*3+0] = cw3[(size_t)(n0 + tid)*3+0];
        w3s[tid*3+1] = cw3[(size_t)(n0 + tid)*3+1];
        w3s[tid*3+2] = cw3[(size_t)(n0 + tid)*3+2];
    }
    __syncthreads();

    const float* alpha = g_ab + 2*DFF;
    const float* beta  = g_ab + 3*DFF;
    float fs[4][2][3];
#pragma unroll
    for (int i = 0; i < 4; i++)
#pragma unroll
        for (int h = 0; h < 2; h++)
#pragma unroll
            for (int c = 0; c < 3; c++) fs[i][h][c] = 0.0f;

#pragma unroll
    for (int j = 0; j < 4; j++) {
        int lc = wc + j*8 + 2*(lane & 3);        // local col 0..127
        int cix = n0 + lc;
        float al0 = alpha[cix], al1 = alpha[cix+1];
        float bt0 = beta[cix],  bt1 = beta[cix+1];
        float w30 = w3s[lc*3+0], w31 = w3s[lc*3+1], w32 = w3s[lc*3+2];
        float u30 = w3s[(lc+1)*3+0], u31 = w3s[(lc+1)*3+1], u32 = w3s[(lc+1)*3+2];
#pragma unroll
        for (int i = 0; i < 4; i++) {
            float v0x = fmaxf(acc[i][j][0]*al0 + bt0, 0.0f);
            float v0y = fmaxf(acc[i][j][1]*al1 + bt1, 0.0f);
            float v1x = fmaxf(acc[i][j][2]*al0 + bt0, 0.0f);
            float v1y = fmaxf(acc[i][j][3]*al1 + bt1, 0.0f);
            fs[i][0][0] += v0x*w30 + v0y*u30;
            fs[i][0][1] += v0x*w31 + v0y*u31;
            fs[i][0][2] += v0x*w32 + v0y*u32;
            fs[i][1][0] += v1x*w30 + v1y*u30;
            fs[i][1][1] += v1x*w31 + v1y*u31;
            fs[i][1][2] += v1x*w32 + v1y*u32;
        }
    }
    // reduce over the 4 lanes sharing a row (lane&3)
#pragma unroll
    for (int o = 1; o <= 2; o <<= 1)
#pragma unroll
        for (int i = 0; i < 4; i++)
#pragma unroll
            for (int h = 0; h < 2; h++)
#pragma unroll
                for (int c = 0; c < 3; c++)
                    fs[i][h][c] += __shfl_xor_sync(0xFFFFFFFFu, fs[i][h][c], o);

    int wrg = wid & 1, wcg = wid >> 1;
    if ((lane & 3) == 0) {
#pragma unroll
        for (int i = 0; i < 4; i++) {
            int rl = i*16 + (lane >> 2);
#pragma unroll
            for (int c = 0; c < 3; c++) {
                part[((wrg*64 + rl)*4 + wcg)*3 + c]     = fs[i][0][c];
                part[((wrg*64 + rl + 8)*4 + wcg)*3 + c] = fs[i][1][c];
            }
        }
    }
    __syncthreads();
    // fixed-order sum over the 4 wc groups; write slab [blockIdx.x]
    float* slab = g_finepart + (size_t)blockIdx.x * ROWS * 3;
    for (int idx = tid; idx < 128*3; idx += 256) {
        int row = idx / 3, c = idx % 3;
        float s = part[(row*4 + 0)*3 + c] + part[(row*4 + 1)*3 + c]
                + part[(row*4 + 2)*3 + c] + part[(row*4 + 3)*3 + c];
        slab[(size_t)(rowBase + row)*3 + c] = s;
    }
}

// ---------------- MLP GEMM: h2m = relu(h1m@w2 + b2) ----------------
__global__ void __launch_bounds__(256) gemm_mlp_kernel(const float* __restrict__ b2) {
    extern __shared__ char smem[];
    uint32_t sb = smem_u32(smem);
    int tid  = threadIdx.x;
    int wid  = tid >> 5, lane = tid & 31;
    int rowBase = blockIdx.y * GM;
    int n0      = blockIdx.x * GN;

    int wr = (wid & 1) * 64;
    int wc = (wid >> 1) * 32;
    int a_row = wr + (lane & 15);
    int a_kb  = (lane >> 4) * 16;
    int b_row = wc + (lane & 7);
    int b_kb  = ((lane >> 3) & 1) * 16;

    float acc[4][4][4];
#pragma unroll
    for (int i = 0; i < 4; i++)
#pragma unroll
        for (int j = 0; j < 4; j++)
#pragma unroll
            for (int q = 0; q < 4; q++) acc[i][j][q] = 0.0f;

    mma_mainloop(g_MAh, g_MAl, g_W2hT, g_W2lT, 48, sb, rowBase, n0, acc,
                 a_row, a_kb, b_row, b_kb);

#pragma unroll
    for (int i = 0; i < 4; i++) {
        int r0 = rowBase + wr + i*16 + (lane >> 2);
#pragma unroll
        for (int j = 0; j < 4; j++) {
            int cix = n0 + wc + j*8 + 2*(lane & 3);
            float bb0 = b2[cix], bb1 = b2[cix+1];
            float2 v0, v1;
            v0.x = fmaxf(acc[i][j][0] + bb0, 0.0f);
            v0.y = fmaxf(acc[i][j][1] + bb1, 0.0f);
            v1.x = fmaxf(acc[i][j][2] + bb0, 0.0f);
            v1.y = fmaxf(acc[i][j][3] + bb1, 0.0f);
            *(float2*)&g_h2m[(size_t)r0      * DFF + cix] = v0;
            *(float2*)&g_h2m[(size_t)(r0+8) * DFF + cix] = v1;
        }
    }
}

// ---------------- fine_reduce: fine = sum(partials) + cb3 + coarse ----------------
__global__ void fine_reduce_kernel(const float* __restrict__ cb3) {
    int row = blockIdx.x * 256 + threadIdx.x;
    if (row >= ROWS) return;
    float s0 = 0.f, s1 = 0.f, s2 = 0.f;
#pragma unroll
    for (int bx = 0; bx < 8; bx++) {
        const float* p = g_finepart + (size_t)bx * ROWS * 3 + (size_t)row * 3;
        s0 += p[0]; s1 += p[1]; s2 += p[2];
    }
    int bp = row / Kk, k = row % Kk, nc = k >> 2;
    const float* cp = &g_coarse[(bp*NCc + nc)*3];
    g_fine[row*3+0] = s0 + cb3[0] + cp[0];
    g_fine[row*3+1] = s1 + cb3[1] + cp[1];
    g_fine[row*3+2] = s2 + cb3[2] + cp[2];
}

// ---------------- Chamfer per-patch partials ----------------
__global__ void chamfer_kernel() {
    int bp  = blockIdx.x;
    int tid = threadIdx.x;   // 64
    __shared__ float f[Kk][3], g[Kk][3];
    __shared__ float r1[Kk], r2[Kk];
    f[tid][0] = g_fine[(bp*Kk + tid)*3+0];
    f[tid][1] = g_fine[(bp*Kk + tid)*3+1];
    f[tid][2] = g_fine[(bp*Kk + tid)*3+2];
    g[tid][0] = g_gxyz[(bp*Kk + tid)*3+0];
    g[tid][1] = g_gxyz[(bp*Kk + tid)*3+1];
    g[tid][2] = g_gxyz[(bp*Kk + tid)*3+2];
    __syncthreads();
    float fx = f[tid][0], fy = f[tid][1], fz = f[tid][2];
    float gx = g[tid][0], gy = g[tid][1], gz = g[tid][2];
    float m1 = FLT_MAX, m2 = FLT_MAX;
    for (int j = 0; j < Kk; j++) {
        float dx = fx - g[j][0], dy = fy - g[j][1], dz = fz - g[j][2];
        m1 = fminf(m1, dx*dx + dy*dy + dz*dz);
        dx = f[j][0] - gx; dy = f[j][1] - gy; dz = f[j][2] - gz;
        m2 = fminf(m2, dx*dx + dy*dy + dz*dz);
    }
    r1[tid] = m1; r2[tid] = m2;
    __syncthreads();
    for (int s = 32; s > 0; s >>= 1) {
        if (tid < s) { r1[tid] += r1[tid+s]; r2[tid] += r2[tid+s]; }
        __syncthreads();
    }
    if (tid == 0) { g_partial[bp] = r1[0]; g_partial[BP + bp] = r2[0]; }
}

// ---------------- deterministic final reduction ----------------
__global__ void final_kernel(float* __restrict__ out, int out_size) {
    __shared__ float s[256];
    int tid = threadIdx.x;
    float a = 0.f;
    for (int i = tid; i < 2*BP; i += 256) a += g_partial[i];
    s[tid] = a;
    __syncthreads();
    for (int st = 128; st > 0; st >>= 1) {
        if (tid < st) s[tid] += s[tid+st];
        __syncthreads();
    }
    if (tid == 0) {
        float loss = s[0] / (float)ROWS;
        for (int i = 0; i < out_size; i++) out[i] = loss;
    }
}

// ---------------- host orchestration ----------------
static inline void launch_gemm(const float* A, const float* B, float* C,
                               int M, int N, int Kd, const float* bias, int relu,
                               __nv_bfloat16* outH = nullptr, __nv_bfloat16* outL = nullptr) {
    dim3 grid((N + BN - 1) / BN, (M + BM - 1) / BM);
    gemm_kernel<<<grid, 256>>>(A, B, C, M, N, Kd, bias, relu, outH, outL);
}

extern "C" void kernel_launch(void* const* d_in, const int* in_sizes, int n_in,
                              void* d_out, int out_size) {
    const float* xyz  = (const float*)d_in[0];
    const float* feat = (const float*)d_in[1];
    const float* w1   = (const float*)d_in[2];
    const float* b1   = (const float*)d_in[3];
    const float* w2   = (const float*)d_in[4];
    const float* b2   = (const float*)d_in[5];
    const float* w3   = (const float*)d_in[6];
    const float* b3   = (const float*)d_in[7];
    const float* cw1  = (const float*)d_in[8];
    const float* cb1  = (const float*)d_in[9];
    const float* g1   = (const float*)d_in[10];
    const float* be1  = (const float*)d_in[11];
    const float* m1   = (const float*)d_in[12];
    const float* v1   = (const float*)d_in[13];
    const float* cw2  = (const float*)d_in[14];
    const float* cb2  = (const float*)d_in[15];
    const float* g2   = (const float*)d_in[16];
    const float* be2  = (const float*)d_in[17];
    const float* m2   = (const float*)d_in[18];
    const float* v2   = (const float*)d_in[19];
    const float* cw3  = (const float*)d_in[20];
    const float* cb3  = (const float*)d_in[21];

    float *pPF, *pH2m, *pCoarse, *pY0;
    __nv_bfloat16 *pBhT, *pBlT, *pW2hT, *pW2lT, *pMAh, *pMAl;
    cudaGetSymbolAddress((void**)&pPF,     g_pf);
    cudaGetSymbolAddress((void**)&pH2m,    g_h2m);
    cudaGetSymbolAddress((void**)&pCoarse, g_coarse);
    cudaGetSymbolAddress((void**)&pY0,     g_Y0);
    cudaGetSymbolAddress((void**)&pBhT,    g_BhT);
    cudaGetSymbolAddress((void**)&pBlT,    g_BlT);
    cudaGetSymbolAddress((void**)&pW2hT,   g_W2hT);
    cudaGetSymbolAddress((void**)&pW2lT,   g_W2lT);
    cudaGetSymbolAddress((void**)&pMAh,    g_MAh);
    cudaGetSymbolAddress((void**)&pMAl,    g_MAl);

    static int smem_set = 0;
    if (!smem_set) {
        cudaFuncSetAttribute(gemm_big_kernel, cudaFuncAttributeMaxDynamicSharedMemorySize, SM_TOTAL);
        cudaFuncSetAttribute(gemm_mlp_kernel, cudaFuncAttributeMaxDynamicSharedMemorySize, SM_TOTAL);
        smem_set = 1;
    }

    prep_kernel<<<1, 1024>>>(g1, be1, m1, v1, cb1, g2, be2, m2, v2, cb2);
    split_w_kernel<<<dim3(32, 32), dim3(32, 32)>>>(cw2, pBhT, pBlT);
    split_w_kernel<<<dim3(32, 32), dim3(32, 32)>>>(w2, pW2hT, pW2lT);
    fps_kernel<<<Bb, 1024>>>(xyz);
    group_kernel<<<BP, 256>>>(xyz, feat);

    // FoldingNet coarse MLP
    launch_gemm(pPF, w1, nullptr, BP, DFF, Dd, b1, 1, pMAh, pMAl);     // h1m (split bf16)
    gemm_mlp_kernel<<<dim3(DFF/GN, BP/GM), 256, SM_TOTAL>>>(b2);       // h2m
    launch_gemm(pH2m, w3, pCoarse, BP, 3*NCc, DFF, b3, 0);             // coarse
    launch_gemm(pPF, cw1, pY0, BP, DFF, Dd, nullptr, 0);               // Y0

    // h1 rows -> split bf16
    h1_build_kernel<<<BP, 256>>>(cw1);

    // big GEMM with fused fine partials
    gemm_big_kernel<<<dim3(DFF/GN, ROWS/GM), 256, SM_TOTAL>>>(cw3);

    // fine + Chamfer
    fine_reduce_kernel<<<(ROWS + 255)/256, 256>>>(cb3);
    chamfer_kernel<<<BP, Kk>>>();
    final_kernel<<<1, 256>>>((float*)d_out, out_size);
}

// round 7
// speedup vs baseline: 3.7814x; 1.0282x over previous
#include <cuda_runtime.h>
#include <cuda_bf16.h>
#include <math.h>
#include <float.h>
#include <stdint.h>

// ---------------- problem constants ----------------
#define Bb   8
#define Nn   4096
#define Dd   128
#define Pp   256
#define Kk   64
#define DFF  1024
#define NCc  16
#define BP   (Bb*Pp)            // 2048 patches
#define ROWS (BP*Kk)            // 131072 fine rows
#define EPSX 1e-5f

// ---------------- scratch (__device__ globals; no allocation allowed) ----------------
__device__ float g_pcx[BP*3];
__device__ float g_pf[BP*Dd];
__device__ float g_gxyz[BP*Kk*3];
__device__ float g_h2m[BP*DFF];
__device__ float g_coarse[BP*NCc*3];
__device__ float g_Y0[BP*DFF];
__device__ __nv_bfloat16 g_Ah[(size_t)ROWS*DFF];   // h1 hi
__device__ __nv_bfloat16 g_Al[(size_t)ROWS*DFF];   // h1 lo
__device__ __nv_bfloat16 g_BhT[DFF*DFF];           // cw2^T hi [n,k]
__device__ __nv_bfloat16 g_BlT[DFF*DFF];           // cw2^T lo
__device__ __nv_bfloat16 g_W2hT[DFF*DFF];          // w2^T hi
__device__ __nv_bfloat16 g_W2lT[DFF*DFF];          // w2^T lo
__device__ __nv_bfloat16 g_MAh[BP*DFF];            // h1m hi (MLP)
__device__ __nv_bfloat16 g_MAl[BP*DFF];            // h1m lo
__device__ float g_finepart[(size_t)8*ROWS*3];     // per-n-slice fine partials
__device__ float g_fine[ROWS*3];
__device__ float g_ab[4*DFF];
__device__ float g_partial[2*BP];

// ---------------- PTX helpers ----------------
static __device__ __forceinline__ uint32_t smem_u32(const void* p) {
    uint32_t a;
    asm("{ .reg .u64 t; cvta.to.shared.u64 t, %1; cvt.u32.u64 %0, t; }" : "=r"(a) : "l"(p));
    return a;
}
static __device__ __forceinline__ void cp16(uint32_t dst, const void* src) {
    asm volatile("cp.async.cg.shared.global [%0], [%1], 16;" :: "r"(dst), "l"(src));
}
#define CP_COMMIT()  asm volatile("cp.async.commit_group;" ::: "memory")
#define CP_WAIT(n)   asm volatile("cp.async.wait_group %0;" :: "n"(n) : "memory")

static __device__ __forceinline__ void ldsm_x4(uint32_t* r, uint32_t addr) {
    asm volatile("ldmatrix.sync.aligned.m8n8.x4.shared.b16 {%0,%1,%2,%3}, [%4];"
                 : "=r"(r[0]), "=r"(r[1]), "=r"(r[2]), "=r"(r[3]) : "r"(addr));
}
static __device__ __forceinline__ void ldsm_x2(uint32_t* r, uint32_t addr) {
    asm volatile("ldmatrix.sync.aligned.m8n8.x2.shared.b16 {%0,%1}, [%2];"
                 : "=r"(r[0]), "=r"(r[1]) : "r"(addr));
}
static __device__ __forceinline__ void mma16816(float* c, const uint32_t* a, const uint32_t* b) {
    asm volatile("mma.sync.aligned.m16n8k16.row.col.f32.bf16.bf16.f32 "
                 "{%0,%1,%2,%3}, {%4,%5,%6,%7}, {%8,%9}, {%0,%1,%2,%3};"
                 : "+f"(c[0]), "+f"(c[1]), "+f"(c[2]), "+f"(c[3])
                 : "r"(a[0]), "r"(a[1]), "r"(a[2]), "r"(a[3]), "r"(b[0]), "r"(b[1]));
}
#define SWZ(off) ((off) ^ (((off) >> 3) & 0x70))

// ---------------- BN fold precompute ----------------
__global__ void prep_kernel(const float* __restrict__ g1, const float* __restrict__ be1,
                            const float* __restrict__ m1, const float* __restrict__ v1,
                            const float* __restrict__ cb1,
                            const float* __restrict__ g2, const float* __restrict__ be2,
                            const float* __restrict__ m2, const float* __restrict__ v2,
                            const float* __restrict__ cb2) {
    int j = blockIdx.x * blockDim.x + threadIdx.x;
    if (j < DFF) {
        float a1 = g1[j] * rsqrtf(v1[j] + EPSX);
        g_ab[j]          = a1;
        g_ab[DFF + j]    = (cb1[j] - m1[j]) * a1 + be1[j];
        float a2 = g2[j] * rsqrtf(v2[j] + EPSX);
        g_ab[2*DFF + j]  = a2;
        g_ab[3*DFF + j]  = (cb2[j] - m2[j]) * a2 + be2[j];
    }
}

// ---------------- split a [DFF,DFF] fp32 weight into transposed bf16 hi/lo ----------------
__global__ void split_w_kernel(const float* __restrict__ W,
                               __nv_bfloat16* __restrict__ outH,
                               __nv_bfloat16* __restrict__ outL) {
    __shared__ float t[32][33];
    int bx = blockIdx.x, by = blockIdx.y;
    int tx = threadIdx.x, ty = threadIdx.y;
    int k = by*32 + ty, n = bx*32 + tx;
    t[ty][tx] = W[(size_t)k*DFF + n];
    __syncthreads();
    int nn = bx*32 + ty, kk = by*32 + tx;
    float v = t[tx][ty];
    __nv_bfloat16 h = __float2bfloat16_rn(v);
    outH[(size_t)nn*DFF + kk] = h;
    outL[(size_t)nn*DFF + kk] = __float2bfloat16_rn(v - __bfloat162float(h));
}

// ---------------- FPS: 256 threads, xyz in smem, atomic-assisted argmax ----------------
// Matches JAX semantics: dist order ((dx*dx+dy*dy)+dz*dz), argmax first-lowest-index.
__global__ void __launch_bounds__(256) fps_kernel(const float* __restrict__ xyz) {
    extern __shared__ float Xs[];              // [Nn*3] = 48KB dynamic
    __shared__ unsigned int sval[4];
    __shared__ int          sidx[4];
    int b = blockIdx.x;
    const float* X = xyz + (size_t)b * Nn * 3;
    int tid = threadIdx.x, lane = tid & 31;

    for (int i = tid; i < Nn*3; i += 256) Xs[i] = X[i];
    if (tid < 4) { sval[tid] = 0u; sidx[tid] = 0x7FFFFFFF; }
    __syncthreads();

    float px[16], py[16], pz[16], mind[16];
#pragma unroll
    for (int i = 0; i < 16; i++) {
        int n = tid + i * 256;
        px[i] = Xs[n*3+0]; py[i] = Xs[n*3+1]; pz[i] = Xs[n*3+2];
        mind[i] = 1e10f;
    }
    if (tid == 0) {
        g_pcx[(b*Pp)*3+0] = Xs[0];
        g_pcx[(b*Pp)*3+1] = Xs[1];
        g_pcx[(b*Pp)*3+2] = Xs[2];
    }
    float lx = Xs[0], ly = Xs[1], lz = Xs[2];

    for (int it = 1; it < Pp; it++) {
        int s = it & 3;
        float mloc = -1.0f;
#pragma unroll
        for (int i = 0; i < 16; i++) {
            float dx = __fsub_rn(px[i], lx);
            float dy = __fsub_rn(py[i], ly);
            float dz = __fsub_rn(pz[i], lz);
            float d  = __fadd_rn(__fadd_rn(__fmul_rn(dx,dx), __fmul_rn(dy,dy)), __fmul_rn(dz,dz));
            float m  = fminf(mind[i], d);
            mind[i]  = m;
            mloc = fmaxf(mloc, m);
        }
#pragma unroll
        for (int o = 16; o > 0; o >>= 1)
            mloc = fmaxf(mloc, __shfl_xor_sync(0xFFFFFFFFu, mloc, o));
        if (lane == 0) atomicMax(&sval[s], __float_as_uint(mloc));
        __syncthreads();
        float mstar = __uint_as_float(sval[s]);
        int ln = 0x7FFFFFFF;
#pragma unroll
        for (int i = 0; i < 16; i++) {
            int n = tid + i * 256;
            if (mind[i] == mstar && n < ln) ln = n;
        }
        if (ln != 0x7FFFFFFF) atomicMin(&sidx[s], ln);
        __syncthreads();
        int w = sidx[s];
        lx = Xs[w*3+0]; ly = Xs[w*3+1]; lz = Xs[w*3+2];
        if (tid == 0) {
            g_pcx[(b*Pp + it)*3+0] = lx;
            g_pcx[(b*Pp + it)*3+1] = ly;
            g_pcx[(b*Pp + it)*3+2] = lz;
            int s2 = (s + 2) & 3;
            sval[s2] = 0u;
            sidx[s2] = 0x7FFFFFFF;
        }
    }
}

// ---------------- kNN grouping (register candidates + u64 shuffle argmin) ----------------
__global__ void group_kernel(const float* __restrict__ xyz, const float* __restrict__ feat) {
    int bp = blockIdx.x;
    int b  = bp / Pp;
    const float* X = xyz + (size_t)b * Nn * 3;
    __shared__ unsigned long long wb[8];
    __shared__ unsigned long long swin;
    __shared__ int sel[Kk];
    __shared__ float mx[2][Dd];
    int tid = threadIdx.x;
    int warp = tid >> 5, lane = tid & 31;

    float cx = g_pcx[bp*3+0], cy = g_pcx[bp*3+1], cz = g_pcx[bp*3+2];
    float d[16];
#pragma unroll
    for (int j = 0; j < 16; j++) {
        int n = tid + j * 256;
        float dx = X[n*3+0] - cx, dy = X[n*3+1] - cy, dz = X[n*3+2] - cz;
        d[j] = dx*dx + dy*dy + dz*dz;
    }

    for (int k = 0; k < Kk; k++) {
        float bd = FLT_MAX; int bj = 0;
#pragma unroll
        for (int j = 0; j < 16; j++)
            if (d[j] < bd) { bd = d[j]; bj = j; }
        unsigned long long key = ((unsigned long long)__float_as_uint(bd) << 32)
                               | (unsigned long long)(uint32_t)(tid + bj*256);
#pragma unroll
        for (int o = 16; o > 0; o >>= 1) {
            unsigned long long v = __shfl_down_sync(0xFFFFFFFFu, key, o);
            if (v < key) key = v;
        }
        if (lane == 0) wb[warp] = key;
        __syncthreads();
        if (warp == 0) {
            unsigned long long k2 = (lane < 8) ? wb[lane] : 0xFFFFFFFFFFFFFFFFull;
#pragma unroll
            for (int o = 4; o > 0; o >>= 1) {
                unsigned long long v = __shfl_down_sync(0xFFFFFFFFu, k2, o);
                if (v < k2) k2 = v;
            }
            if (lane == 0) swin = k2;
        }
        __syncthreads();
        int widx = (int)(swin & 0xFFFFFFFFu);
        if (tid == 0) sel[k] = widx;
        if ((widx & 255) == tid) {
            int jw = widx >> 8;
#pragma unroll
            for (int j = 0; j < 16; j++)
                if (j == jw) d[j] = FLT_MAX;
        }
        __syncthreads();
    }

    if (tid < Kk) {
        int idx = sel[tid];
        g_gxyz[(bp*Kk + tid)*3+0] = X[idx*3+0] - cx;
        g_gxyz[(bp*Kk + tid)*3+1] = X[idx*3+1] - cy;
        g_gxyz[(bp*Kk + tid)*3+2] = X[idx*3+2] - cz;
    }
    __syncthreads();

    const float* F = feat + (size_t)b * Nn * Dd;
    int half = tid >> 7, dd2 = tid & 127;
    float m = -FLT_MAX;
#pragma unroll 4
    for (int k = half*32; k < half*32 + 32; k++)
        m = fmaxf(m, F[(size_t)sel[k] * Dd + dd2]);
    mx[half][dd2] = m;
    __syncthreads();
    if (half == 0)
        g_pf[bp*Dd + dd2] = fmaxf(mx[0][dd2], mx[1][dd2]);
}

// ---------------- generic fp32 tiled GEMM (small matrices; optional split-bf16 out) ----------------
#define BM 128
#define BN 128
#define BKg 8
#define TM 8
#define TN 8
__global__ void gemm_kernel(const float* __restrict__ A, const float* __restrict__ B,
                            float* __restrict__ C, int M, int N, int Kd,
                            const float* __restrict__ bias, int relu,
                            __nv_bfloat16* __restrict__ outH, __nv_bfloat16* __restrict__ outL) {
    __shared__ float As[BKg][BM];
    __shared__ float Bs[BKg][BN];
    int tid = threadIdx.x;
    int tx = tid % 16, ty = tid / 16;
    int rowBase = blockIdx.y * BM;
    int colBase = blockIdx.x * BN;

    float acc[TM][TN];
#pragma unroll
    for (int i = 0; i < TM; i++)
#pragma unroll
        for (int j = 0; j < TN; j++) acc[i][j] = 0.0f;

    int aRow  = tid >> 1;
    int aCol4 = (tid & 1) * 4;
    int bRow  = tid >> 5;
    int bCol4 = (tid & 31) * 4;

    for (int k0 = 0; k0 < Kd; k0 += BKg) {
        {
            int gr = rowBase + aRow;
#pragma unroll
            for (int i = 0; i < 4; i++) {
                int gk = k0 + aCol4 + i;
                float v = (gr < M && gk < Kd) ? A[(size_t)gr * Kd + gk] : 0.0f;
                As[aCol4 + i][aRow] = v;
            }
        }
        {
            int gk = k0 + bRow;
#pragma unroll
            for (int i = 0; i < 4; i++) {
                int gc = colBase + bCol4 + i;
                float v = (gk < Kd && gc < N) ? B[(size_t)gk * N + gc] : 0.0f;
                Bs[bRow][bCol4 + i] = v;
            }
        }
        __syncthreads();
#pragma unroll
        for (int kk = 0; kk < BKg; kk++) {
            float a[TM], bb[TN];
#pragma unroll
            for (int i = 0; i < TM; i++) a[i] = As[kk][ty*TM + i];
#pragma unroll
            for (int j = 0; j < TN; j++) bb[j] = Bs[kk][tx*TN + j];
#pragma unroll
            for (int i = 0; i < TM; i++)
#pragma unroll
                for (int j = 0; j < TN; j++) acc[i][j] += a[i] * bb[j];
        }
        __syncthreads();
    }

#pragma unroll
    for (int i = 0; i < TM; i++) {
        int r = rowBase + ty*TM + i;
        if (r >= M) continue;
#pragma unroll
        for (int j = 0; j < TN; j++) {
            int c = colBase + tx*TN + j;
            if (c >= N) continue;
            float v = acc[i][j];
            if (bias) v += bias[c];
            if (relu) v = fmaxf(v, 0.0f);
            if (outH) {
                __nv_bfloat16 h = __float2bfloat16_rn(v);
                outH[(size_t)r * N + c] = h;
                outL[(size_t)r * N + c] = __float2bfloat16_rn(v - __bfloat162float(h));
            } else {
                C[(size_t)r * N + c] = v;
            }
        }
    }
}

// ---------------- build h1 rows -> split bf16 ----------------
__global__ void h1_build_kernel(const float* __restrict__ cw1) {
    int bp  = blockIdx.x;
    int tid = threadIdx.x;               // 256
    __shared__ float y0[DFF], c0[DFF], c1[DFF], c2[DFF], c3[DFF], c4[DFF], sal[DFF], sbt[DFF];
    __shared__ float crs[NCc*3];

    for (int j = tid; j < DFF; j += 256) {
        y0[j] = g_Y0[(size_t)bp*DFF + j];
        c0[j] = cw1[(size_t)128*DFF + j];
        c1[j] = cw1[(size_t)129*DFF + j];
        c2[j] = cw1[(size_t)130*DFF + j];
        c3[j] = cw1[(size_t)131*DFF + j];
        c4[j] = cw1[(size_t)132*DFF + j];
        sal[j] = g_ab[j];
        sbt[j] = g_ab[DFF + j];
    }
    if (tid < NCc*3) crs[tid] = g_coarse[bp*NCc*3 + tid];
    __syncthreads();

    int j0 = tid * 4;
    float4 vy = *(float4*)&y0[j0];
    float4 v0 = *(float4*)&c0[j0];
    float4 v1 = *(float4*)&c1[j0];
    float4 v2 = *(float4*)&c2[j0];
    float4 v3 = *(float4*)&c3[j0];
    float4 v4 = *(float4*)&c4[j0];
    float4 va = *(float4*)&sal[j0];
    float4 vb = *(float4*)&sbt[j0];

    for (int k = 0; k < Kk; k++) {
        int sidx = k & 3;
        float s0 = (sidx & 1) ?  0.05f : -0.05f;
        float s1 = (sidx & 2) ?  0.05f : -0.05f;
        int nc = k >> 2;
        float pxv = crs[nc*3+0], pyv = crs[nc*3+1], pzv = crs[nc*3+2];
        size_t rowoff = ((size_t)bp * Kk + k) * DFF + j0;
        uint32_t hpk[2], lpk[2];
        __nv_bfloat16 h2[2], l2[2];
#pragma unroll
        for (int q = 0; q < 4; q++) {
            float yy = (&vy.x)[q], w0 = (&v0.x)[q], w1 = (&v1.x)[q],
                  w2 = (&v2.x)[q], w3 = (&v3.x)[q], w4 = (&v4.x)[q],
                  al = (&va.x)[q], bt = (&vb.x)[q];
            float pre = yy + s0*w0 + s1*w1 + pxv*w2 + pyv*w3 + pzv*w4;
            float act = fmaxf(pre * al + bt, 0.0f);
            __nv_bfloat16 h = __float2bfloat16_rn(act);
            float hi  = __bfloat162float(h);
            h2[q & 1] = h;
            l2[q & 1] = __float2bfloat16_rn(act - hi);
            if (q & 1) {
                hpk[q>>1] = ((uint32_t)*(uint16_t*)&h2[1] << 16) | *(uint16_t*)&h2[0];
                lpk[q>>1] = ((uint32_t)*(uint16_t*)&l2[1] << 16) | *(uint16_t*)&l2[0];
            }
        }
        *(uint2*)&g_Ah[rowoff] = make_uint2(hpk[0], hpk[1]);
        *(uint2*)&g_Al[rowoff] = make_uint2(lpk[0], lpk[1]);
    }
}

// ---------------- shared split-bf16 mma mainloop (CTA 128x128, BK=64) ----------------
#define GM 128
#define GN 128
#define SM_ASZ   (GM*128)
#define SM_BSZ   (GN*128)
#define SM_STAGE (SM_ASZ + SM_BSZ)
#define SM_TOTAL (2*SM_STAGE)        // 65536

static __device__ __forceinline__ void load_chunk_p(uint32_t sb, int s,
        const __nv_bfloat16* __restrict__ Asrc, const __nv_bfloat16* __restrict__ Bsrc,
        int gk, int rowBase, int n0) {
    uint32_t aBase = sb + s * SM_STAGE;
    uint32_t bBase = aBase + SM_ASZ;
    int tid = threadIdx.x;
#pragma unroll
    for (int i = 0; i < 4; i++) {
        int t = tid + i * 256;
        int tr = t >> 3, c8 = t & 7;
        const __nv_bfloat16* src = Asrc + (size_t)(rowBase + tr) * DFF + gk + c8 * 8;
        uint32_t off = tr * 128 + c8 * 16;
        cp16(aBase + SWZ(off), src);
    }
#pragma unroll
    for (int i = 0; i < 4; i++) {
        int t = tid + i * 256;
        int nr = t >> 3, c8 = t & 7;
        const __nv_bfloat16* src = Bsrc + (size_t)(n0 + nr) * DFF + gk + c8 * 8;
        uint32_t off = nr * 128 + c8 * 16;
        cp16(bBase + SWZ(off), src);
    }
    CP_COMMIT();
}

static __device__ __forceinline__ void pick_chunk(int c,
        const __nv_bfloat16* Ah, const __nv_bfloat16* Al,
        const __nv_bfloat16* BhT, const __nv_bfloat16* BlT,
        const __nv_bfloat16** As_, const __nv_bfloat16** Bs_, int* gk) {
    int kb = c / 3, wh = c - kb*3;
    *As_ = (wh < 2) ? Ah : Al;
    *Bs_ = (wh == 1) ? BlT : BhT;
    *gk = kb * 64;
}

static __device__ __forceinline__ void mma_mainloop(
        const __nv_bfloat16* __restrict__ Ah, const __nv_bfloat16* __restrict__ Al,
        const __nv_bfloat16* __restrict__ BhT, const __nv_bfloat16* __restrict__ BlT,
        int nchunk, uint32_t sb, int rowBase, int n0, float acc[4][4][4],
        int a_row, int a_kb, int b_row, int b_kb) {
    const __nv_bfloat16 *As_, *Bs_;
    int gk;
    pick_chunk(0, Ah, Al, BhT, BlT, &As_, &Bs_, &gk);
    load_chunk_p(sb, 0, As_, Bs_, gk, rowBase, n0);
    pick_chunk(1, Ah, Al, BhT, BlT, &As_, &Bs_, &gk);
    load_chunk_p(sb, 1, As_, Bs_, gk, rowBase, n0);

    for (int c = 0; c < nchunk; c++) {
        int s = c & 1;
        if (c < nchunk - 1) { CP_WAIT(1); } else { CP_WAIT(0); }
        __syncthreads();
        uint32_t aBase = sb + s * SM_STAGE;
        uint32_t bBase = aBase + SM_ASZ;
#pragma unroll
        for (int ks = 0; ks < 4; ks++) {
            uint32_t aF[4][4], bF[4][2];
#pragma unroll
            for (int i = 0; i < 4; i++) {
                uint32_t off = (uint32_t)(a_row + i*16) * 128 + ks*32 + a_kb;
                ldsm_x4(aF[i], aBase + SWZ(off));
            }
#pragma unroll
            for (int j = 0; j < 4; j++) {
                uint32_t off = (uint32_t)(b_row + j*8) * 128 + ks*32 + b_kb;
                ldsm_x2(bF[j], bBase + SWZ(off));
            }
#pragma unroll
            for (int i = 0; i < 4; i++)
#pragma unroll
                for (int j = 0; j < 4; j++)
                    mma16816(acc[i][j], aF[i], bF[j]);
        }
        __syncthreads();
        if (c + 2 < nchunk) {
            pick_chunk(c + 2, Ah, Al, BhT, BlT, &As_, &Bs_, &gk);
            load_chunk_p(sb, s, As_, Bs_, gk, rowBase, n0);
        }
    }
}

// ---------------- BIG GEMM: h2 = relu(bn(h1@cw2)), fused fine partials (no H2!) ----------------
__global__ void __launch_bounds__(256, 2) gemm_big_kernel(const float* __restrict__ cw3) {
    extern __shared__ char smem[];
    uint32_t sb = smem_u32(smem);
    int tid  = threadIdx.x;
    int wid  = tid >> 5, lane = tid & 31;
    int rowBase = blockIdx.y * GM;
    int n0      = blockIdx.x * GN;

    int wr = (wid & 1) * 64;
    int wc = (wid >> 1) * 32;
    int a_row = wr + (lane & 15);
    int a_kb  = (lane >> 4) * 16;
    int b_row = wc + (lane & 7);
    int b_kb  = ((lane >> 3) & 1) * 16;

    float acc[4][4][4];
#pragma unroll
    for (int i = 0; i < 4; i++)
#pragma unroll
        for (int j = 0; j < 4; j++)
#pragma unroll
            for (int q = 0; q < 4; q++) acc[i][j][q] = 0.0f;

    mma_mainloop(g_Ah, g_Al, g_BhT, g_BlT, 48, sb, rowBase, n0, acc,
                 a_row, a_kb, b_row, b_kb);

    // ---- epilogue: v = relu(acc*alpha+beta); fine partial = v @ cw3[n0:n0+128] ----
    float* w3s  = (float*)smem;                  // [128][3]
    float* part = (float*)(smem + 2048);         // [2][64][4][3]
    if (tid < 128) {
        w3s[tid*3+0] = cw3[(size_t)(n0 + tid)*3+0];
        w3s[tid*3+1] = cw3[(size_t)(n0 + tid)*3+1];
        w3s[tid*3+2] = cw3[(size_t)(n0 + tid)*3+2];
    }
    __syncthreads();

    const float* alpha = g_ab + 2*DFF;
    const float* beta  = g_ab + 3*DFF;
    float fs[4][2][3];
#pragma unroll
    for (int i = 0; i < 4; i++)
#pragma unroll
        for (int h = 0; h < 2; h++)
#pragma unroll
            for (int c = 0; c < 3; c++) fs[i][h][c] = 0.0f;

#pragma unroll
    for (int j = 0; j < 4; j++) {
        int lc = wc + j*8 + 2*(lane & 3);
        int cix = n0 + lc;
        float al0 = alpha[cix], al1 = alpha[cix+1];
        float bt0 = beta[cix],  bt1 = beta[cix+1];
        float w30 = w3s[lc*3+0], w31 = w3s[lc*3+1], w32 = w3s[lc*3+2];
        float u30 = w3s[(lc+1)*3+0], u31 = w3s[(lc+1)*3+1], u32 = w3s[(lc+1)*3+2];
#pragma unroll
        for (int i = 0; i < 4; i++) {
            float v0x = fmaxf(acc[i][j][0]*al0 + bt0, 0.0f);
            float v0y = fmaxf(acc[i][j][1]*al1 + bt1, 0.0f);
            float v1x = fmaxf(acc[i][j][2]*al0 + bt0, 0.0f);
            float v1y = fmaxf(acc[i][j][3]*al1 + bt1, 0.0f);
            fs[i][0][0] += v0x*w30 + v0y*u30;
            fs[i][0][1] += v0x*w31 + v0y*u31;
            fs[i][0][2] += v0x*w32 + v0y*u32;
            fs[i][1][0] += v1x*w30 + v1y*u30;
            fs[i][1][1] += v1x*w31 + v1y*u31;
            fs[i][1][2] += v1x*w32 + v1y*u32;
        }
    }
#pragma unroll
    for (int o = 1; o <= 2; o <<= 1)
#pragma unroll
        for (int i = 0; i < 4; i++)
#pragma unroll
            for (int h = 0; h < 2; h++)
#pragma unroll
                for (int c = 0; c < 3; c++)
                    fs[i][h][c] += __shfl_xor_sync(0xFFFFFFFFu, fs[i][h][c], o);

    int wrg = wid & 1, wcg = wid >> 1;
    if ((lane & 3) == 0) {
#pragma unroll
        for (int i = 0; i < 4; i++) {
            int rl = i*16 + (lane >> 2);
#pragma unroll
            for (int c = 0; c < 3; c++) {
                part[((wrg*64 + rl)*4 + wcg)*3 + c]     = fs[i][0][c];
                part[((wrg*64 + rl + 8)*4 + wcg)*3 + c] = fs[i][1][c];
            }
        }
    }
    __syncthreads();
    float* slab = g_finepart + (size_t)blockIdx.x * ROWS * 3;
    for (int idx = tid; idx < 128*3; idx += 256) {
        int row = idx / 3, c = idx % 3;
        float s = part[(row*4 + 0)*3 + c] + part[(row*4 + 1)*3 + c]
                + part[(row*4 + 2)*3 + c] + part[(row*4 + 3)*3 + c];
        slab[(size_t)(rowBase + row)*3 + c] = s;
    }
}

// ---------------- MLP GEMM: h2m = relu(h1m@w2 + b2) ----------------
__global__ void __launch_bounds__(256, 2) gemm_mlp_kernel(const float* __restrict__ b2) {
    extern __shared__ char smem[];
    uint32_t sb = smem_u32(smem);
    int tid  = threadIdx.x;
    int wid  = tid >> 5, lane = tid & 31;
    int rowBase = blockIdx.y * GM;
    int n0      = blockIdx.x * GN;

    int wr = (wid & 1) * 64;
    int wc = (wid >> 1) * 32;
    int a_row = wr + (lane & 15);
    int a_kb  = (lane >> 4) * 16;
    int b_row = wc + (lane & 7);
    int b_kb  = ((lane >> 3) & 1) * 16;

    float acc[4][4][4];
#pragma unroll
    for (int i = 0; i < 4; i++)
#pragma unroll
        for (int j = 0; j < 4; j++)
#pragma unroll
            for (int q = 0; q < 4; q++) acc[i][j][q] = 0.0f;

    mma_mainloop(g_MAh, g_MAl, g_W2hT, g_W2lT, 48, sb, rowBase, n0, acc,
                 a_row, a_kb, b_row, b_kb);

#pragma unroll
    for (int i = 0; i < 4; i++) {
        int r0 = rowBase + wr + i*16 + (lane >> 2);
#pragma unroll
        for (int j = 0; j < 4; j++) {
            int cix = n0 + wc + j*8 + 2*(lane & 3);
            float bb0 = b2[cix], bb1 = b2[cix+1];
            float2 v0, v1;
            v0.x = fmaxf(acc[i][j][0] + bb0, 0.0f);
            v0.y = fmaxf(acc[i][j][1] + bb1, 0.0f);
            v1.x = fmaxf(acc[i][j][2] + bb0, 0.0f);
            v1.y = fmaxf(acc[i][j][3] + bb1, 0.0f);
            *(float2*)&g_h2m[(size_t)r0      * DFF + cix] = v0;
            *(float2*)&g_h2m[(size_t)(r0+8) * DFF + cix] = v1;
        }
    }
}

// ---------------- fine_reduce: fine = sum(partials) + cb3 + coarse ----------------
__global__ void fine_reduce_kernel(const float* __restrict__ cb3) {
    int row = blockIdx.x * 256 + threadIdx.x;
    if (row >= ROWS) return;
    float s0 = 0.f, s1 = 0.f, s2 = 0.f;
#pragma unroll
    for (int bx = 0; bx < 8; bx++) {
        const float* p = g_finepart + (size_t)bx * ROWS * 3 + (size_t)row * 3;
        s0 += p[0]; s1 += p[1]; s2 += p[2];
    }
    int bp = row / Kk, k = row % Kk, nc = k >> 2;
    const float* cp = &g_coarse[(bp*NCc + nc)*3];
    g_fine[row*3+0] = s0 + cb3[0] + cp[0];
    g_fine[row*3+1] = s1 + cb3[1] + cp[1];
    g_fine[row*3+2] = s2 + cb3[2] + cp[2];
}

// ---------------- Chamfer per-patch partials ----------------
__global__ void chamfer_kernel() {
    int bp  = blockIdx.x;
    int tid = threadIdx.x;   // 64
    __shared__ float f[Kk][3], g[Kk][3];
    __shared__ float r1[Kk], r2[Kk];
    f[tid][0] = g_fine[(bp*Kk + tid)*3+0];
    f[tid][1] = g_fine[(bp*Kk + tid)*3+1];
    f[tid][2] = g_fine[(bp*Kk + tid)*3+2];
    g[tid][0] = g_gxyz[(bp*Kk + tid)*3+0];
    g[tid][1] = g_gxyz[(bp*Kk + tid)*3+1];
    g[tid][2] = g_gxyz[(bp*Kk + tid)*3+2];
    __syncthreads();
    float fx = f[tid][0], fy = f[tid][1], fz = f[tid][2];
    float gx = g[tid][0], gy = g[tid][1], gz = g[tid][2];
    float m1 = FLT_MAX, m2 = FLT_MAX;
    for (int j = 0; j < Kk; j++) {
        float dx = fx - g[j][0], dy = fy - g[j][1], dz = fz - g[j][2];
        m1 = fminf(m1, dx*dx + dy*dy + dz*dz);
        dx = f[j][0] - gx; dy = f[j][1] - gy; dz = f[j][2] - gz;
        m2 = fminf(m2, dx*dx + dy*dy + dz*dz);
    }
    r1[tid] = m1; r2[tid] = m2;
    __syncthreads();
    for (int s = 32; s > 0; s >>= 1) {
        if (tid < s) { r1[tid] += r1[tid+s]; r2[tid] += r2[tid+s]; }
        __syncthreads();
    }
    if (tid == 0) { g_partial[bp] = r1[0]; g_partial[BP + bp] = r2[0]; }
}

// ---------------- deterministic final reduction ----------------
__global__ void final_kernel(float* __restrict__ out, int out_size) {
    __shared__ float s[256];
    int tid = threadIdx.x;
    float a = 0.f;
    for (int i = tid; i < 2*BP; i += 256) a += g_partial[i];
    s[tid] = a;
    __syncthreads();
    for (int st = 128; st > 0; st >>= 1) {
        if (tid < st) s[tid] += s[tid+st];
        __syncthreads();
    }
    if (tid == 0) {
        float loss = s[0] / (float)ROWS;
        for (int i = 0; i < out_size; i++) out[i] = loss;
    }
}

// ---------------- host orchestration ----------------
static inline void launch_gemm(const float* A, const float* B, float* C,
                               int M, int N, int Kd, const float* bias, int relu,
                               __nv_bfloat16* outH = nullptr, __nv_bfloat16* outL = nullptr) {
    dim3 grid((N + BN - 1) / BN, (M + BM - 1) / BM);
    gemm_kernel<<<grid, 256>>>(A, B, C, M, N, Kd, bias, relu, outH, outL);
}

extern "C" void kernel_launch(void* const* d_in, const int* in_sizes, int n_in,
                              void* d_out, int out_size) {
    const float* xyz  = (const float*)d_in[0];
    const float* feat = (const float*)d_in[1];
    const float* w1   = (const float*)d_in[2];
    const float* b1   = (const float*)d_in[3];
    const float* w2   = (const float*)d_in[4];
    const float* b2   = (const float*)d_in[5];
    const float* w3   = (const float*)d_in[6];
    const float* b3   = (const float*)d_in[7];
    const float* cw1  = (const float*)d_in[8];
    const float* cb1  = (const float*)d_in[9];
    const float* g1   = (const float*)d_in[10];
    const float* be1  = (const float*)d_in[11];
    const float* m1   = (const float*)d_in[12];
    const float* v1   = (const float*)d_in[13];
    const float* cw2  = (const float*)d_in[14];
    const float* cb2  = (const float*)d_in[15];
    const float* g2   = (const float*)d_in[16];
    const float* be2  = (const float*)d_in[17];
    const float* m2   = (const float*)d_in[18];
    const float* v2   = (const float*)d_in[19];
    const float* cw3  = (const float*)d_in[20];
    const float* cb3  = (const float*)d_in[21];

    float *pPF, *pH2m, *pCoarse, *pY0;
    __nv_bfloat16 *pBhT, *pBlT, *pW2hT, *pW2lT, *pMAh, *pMAl;
    cudaGetSymbolAddress((void**)&pPF,     g_pf);
    cudaGetSymbolAddress((void**)&pH2m,    g_h2m);
    cudaGetSymbolAddress((void**)&pCoarse, g_coarse);
    cudaGetSymbolAddress((void**)&pY0,     g_Y0);
    cudaGetSymbolAddress((void**)&pBhT,    g_BhT);
    cudaGetSymbolAddress((void**)&pBlT,    g_BlT);
    cudaGetSymbolAddress((void**)&pW2hT,   g_W2hT);
    cudaGetSymbolAddress((void**)&pW2lT,   g_W2lT);
    cudaGetSymbolAddress((void**)&pMAh,    g_MAh);
    cudaGetSymbolAddress((void**)&pMAl,    g_MAl);

    static int smem_set = 0;
    if (!smem_set) {
        cudaFuncSetAttribute(gemm_big_kernel, cudaFuncAttributeMaxDynamicSharedMemorySize, SM_TOTAL);
        cudaFuncSetAttribute(gemm_mlp_kernel, cudaFuncAttributeMaxDynamicSharedMemorySize, SM_TOTAL);
        cudaFuncSetAttribute(fps_kernel,      cudaFuncAttributeMaxDynamicSharedMemorySize, Nn*3*sizeof(float) + 1024);
        smem_set = 1;
    }

    prep_kernel<<<1, 1024>>>(g1, be1, m1, v1, cb1, g2, be2, m2, v2, cb2);
    split_w_kernel<<<dim3(32, 32), dim3(32, 32)>>>(cw2, pBhT, pBlT);
    split_w_kernel<<<dim3(32, 32), dim3(32, 32)>>>(w2, pW2hT, pW2lT);
    fps_kernel<<<Bb, 256, Nn*3*sizeof(float)>>>(xyz);
    group_kernel<<<BP, 256>>>(xyz, feat);

    // FoldingNet coarse MLP
    launch_gemm(pPF, w1, nullptr, BP, DFF, Dd, b1, 1, pMAh, pMAl);     // h1m (split bf16)
    gemm_mlp_kernel<<<dim3(DFF/GN, BP/GM), 256, SM_TOTAL>>>(b2);       // h2m
    launch_gemm(pH2m, w3, pCoarse, BP, 3*NCc, DFF, b3, 0);             // coarse
    launch_gemm(pPF, cw1, pY0, BP, DFF, Dd, nullptr, 0);               // Y0

    // h1 rows -> split bf16
    h1_build_kernel<<<BP, 256>>>(cw1);

    // big GEMM with fused fine partials
    gemm_big_kernel<<<dim3(DFF/GN, ROWS/GM), 256, SM_TOTAL>>>(cw3);

    // fine + Chamfer
    fine_reduce_kernel<<<(ROWS + 255)/256, 256>>>(cb3);
    chamfer_kernel<<<BP, Kk>>>();
    final_kernel<<<1, 256>>>((float*)d_out, out_size);
}